// round 12
// baseline (speedup 1.0000x reference)
#include <cuda_runtime.h>
#include <cuda_bf16.h>
#include <math.h>
#include <stdint.h>

#define T_SEQ   2048
#define D_MODEL 1024
#define NH      16
#define DH      64
#define CHUNK   64
#define NCHUNK  (T_SEQ / CHUNK)   // 32
#define KT      32                // K elems per tile chunk (64B rows)
#define NKC     (D_MODEL / KT)    // 32 mainloop iterations
#define TILE_B  8192              // 128 rows * 64B
#define STAGE_B 32768             // Ahi, Alo, Whi, Wlo tiles
#define NST     3

// ---------------- scratch (static __device__ arrays; no allocation) ----------
__device__ __align__(256) float g_q  [T_SEQ * D_MODEL];
__device__ __align__(256) float g_g  [T_SEQ * D_MODEL];
__device__ __align__(256) float g_kf [T_SEQ * D_MODEL];
__device__ __align__(256) float g_v  [T_SEQ * D_MODEL];
__device__ __align__(256) float g_Sc  [NH * NCHUNK * DH * DH];
__device__ __align__(256) float g_Spre[NH * NCHUNK * DH * DH];
__device__ __align__(256) float g_zc  [NH * NCHUNK * DH];
__device__ __align__(256) float g_zpre[NH * NCHUNK * DH];
__device__ __align__(256) __nv_bfloat16 g_xhi [T_SEQ * D_MODEL];
__device__ __align__(256) __nv_bfloat16 g_xlo [T_SEQ * D_MODEL];
__device__ __align__(256) __nv_bfloat16 g_Whi [5 * D_MODEL * D_MODEL];
__device__ __align__(256) __nv_bfloat16 g_Wlo [5 * D_MODEL * D_MODEL];
__device__ __align__(256) __nv_bfloat16 g_athi[T_SEQ * D_MODEL];
__device__ __align__(256) __nv_bfloat16 g_atlo[T_SEQ * D_MODEL];

__device__ __forceinline__ float softplus_f(float x) {
    return (x > 20.f) ? x : log1pf(expf(x));
}

__device__ __forceinline__ void split4(float4 v, __nv_bfloat162* hi2, __nv_bfloat162* lo2) {
    __nv_bfloat16 h0 = __float2bfloat16_rn(v.x), h1 = __float2bfloat16_rn(v.y);
    __nv_bfloat16 h2 = __float2bfloat16_rn(v.z), h3 = __float2bfloat16_rn(v.w);
    hi2[0].x = h0; hi2[0].y = h1; hi2[1].x = h2; hi2[1].y = h3;
    lo2[0].x = __float2bfloat16_rn(v.x - __bfloat162float(h0));
    lo2[0].y = __float2bfloat16_rn(v.y - __bfloat162float(h1));
    lo2[1].x = __float2bfloat16_rn(v.z - __bfloat162float(h2));
    lo2[1].y = __float2bfloat16_rn(v.w - __bfloat162float(h3));
}

// =============== split kernels: fp32 -> (hi, lo) bf16 =======================
__global__ __launch_bounds__(256) void split_kernel(const float* __restrict__ src,
                                                    __nv_bfloat16* __restrict__ hi,
                                                    __nv_bfloat16* __restrict__ lo, int n4) {
    int i = blockIdx.x * 256 + threadIdx.x;
    if (i >= n4) return;
    __nv_bfloat162 H[2], L[2];
    split4(((const float4*)src)[i], H, L);
    ((__nv_bfloat162*)hi)[i * 2 + 0] = H[0];
    ((__nv_bfloat162*)hi)[i * 2 + 1] = H[1];
    ((__nv_bfloat162*)lo)[i * 2 + 0] = L[0];
    ((__nv_bfloat162*)lo)[i * 2 + 1] = L[1];
}

__global__ __launch_bounds__(256) void split4w_kernel(
    const float* __restrict__ s0, const float* __restrict__ s1,
    const float* __restrict__ s2, const float* __restrict__ s3)
{
    const float* srcs[4] = {s0, s1, s2, s3};
    int z = blockIdx.y;
    int i = blockIdx.x * 256 + threadIdx.x;
    size_t off = (size_t)z * (D_MODEL * D_MODEL / 4);
    __nv_bfloat162 H[2], L[2];
    split4(((const float4*)srcs[z])[i], H, L);
    ((__nv_bfloat162*)g_Whi)[(off + i) * 2 + 0] = H[0];
    ((__nv_bfloat162*)g_Whi)[(off + i) * 2 + 1] = H[1];
    ((__nv_bfloat162*)g_Wlo)[(off + i) * 2 + 0] = L[0];
    ((__nv_bfloat162*)g_Wlo)[(off + i) * 2 + 1] = L[1];
}

// ======== fused 3-term split-bf16 GEMM: C = A * W^T + activation ============
// Single-barrier pipeline: wait -> sync -> issue(it+2) -> compute. (round-10 winner)
__device__ __forceinline__ uint32_t sw64(int row, int j) {
    return (uint32_t)(row * 64 + 16 * (j ^ ((row >> 1) & 3)));
}

__global__ __launch_bounds__(256, 2) void mma_gemm_kernel(
    const __nv_bfloat16* __restrict__ Ahi, const __nv_bfloat16* __restrict__ Alo,
    const float* __restrict__ bias,
    float* C0, float* C1, float* C2, float* C3, int wbase)
{
    extern __shared__ __nv_bfloat16 sm[];
    const int tid = threadIdx.x, lane = tid & 31, wid = tid >> 5;
    const int g = lane >> 2, t = lane & 3;
    const int warpM = (wid & 1) * 64, warpN = (wid >> 1) * 32;
    const int z = blockIdx.z, widx = wbase + z;
    const int m0 = blockIdx.y * 128, n0 = blockIdx.x * 128;

    const __nv_bfloat16* Wh = g_Whi + (size_t)widx * D_MODEL * D_MODEL;
    const __nv_bfloat16* Wl = g_Wlo + (size_t)widx * D_MODEL * D_MODEL;
    float* Cs[4] = {C0, C1, C2, C3};
    float* C = Cs[z];
    const int mode = (widx <= 1) ? 1 : (widx == 3 ? 2 : 0);

    float acc[4][4][4];
    #pragma unroll
    for (int a = 0; a < 4; a++)
        #pragma unroll
        for (int b = 0; b < 4; b++)
            #pragma unroll
            for (int c = 0; c < 4; c++) acc[a][b][c] = 0.f;

    const uint32_t smb = (uint32_t)__cvta_generic_to_shared(sm);
    const int arow = (lane & 7) + ((lane >> 3) & 1) * 8;
    const int ajl  = lane >> 4;
    const int bsel = lane >> 3;
    const int brow = (lane & 7) + ((bsel >> 1) & 1) * 8;
    const int bjl  = bsel & 1;

    auto issue = [&](int kc) {
        const uint32_t sbase = smb + (kc % NST) * STAGE_B;
        #pragma unroll
        for (int r = 0; r < 2; r++) {
            int id = tid + r * 256, row = id >> 2, c = id & 3;
            uint32_t off = sw64(row, c);
            size_t ga = (size_t)(m0 + row) * D_MODEL + kc * KT + c * 8;
            size_t gb = (size_t)(n0 + row) * D_MODEL + kc * KT + c * 8;
            asm volatile("cp.async.cg.shared.global [%0], [%1], 16;" :: "r"(sbase + off),              "l"((const void*)(Ahi + ga)));
            asm volatile("cp.async.cg.shared.global [%0], [%1], 16;" :: "r"(sbase + TILE_B + off),     "l"((const void*)(Alo + ga)));
            asm volatile("cp.async.cg.shared.global [%0], [%1], 16;" :: "r"(sbase + 2 * TILE_B + off), "l"((const void*)(Wh + gb)));
            asm volatile("cp.async.cg.shared.global [%0], [%1], 16;" :: "r"(sbase + 3 * TILE_B + off), "l"((const void*)(Wl + gb)));
        }
        asm volatile("cp.async.commit_group;" ::: "memory");
    };

    issue(0); issue(1);

    for (int it = 0; it < NKC; it++) {
        if (it < NKC - 1) asm volatile("cp.async.wait_group 1;" ::: "memory");
        else              asm volatile("cp.async.wait_group 0;" ::: "memory");
        __syncthreads();
        if (it + 2 < NKC) issue(it + 2);

        const uint32_t sbase = smb + (it % NST) * STAGE_B;
        #pragma unroll
        for (int ks = 0; ks < 2; ks++) {
            uint32_t ahif[4][4], alof[4][4], bf[4][2];
            #pragma unroll
            for (int mt = 0; mt < 4; mt++) {
                uint32_t addr = sbase + sw64(warpM + mt * 16 + arow, ks * 2 + ajl);
                asm volatile("ldmatrix.sync.aligned.m8n8.x4.shared.b16 {%0,%1,%2,%3}, [%4];"
                             : "=r"(ahif[mt][0]), "=r"(ahif[mt][1]), "=r"(ahif[mt][2]), "=r"(ahif[mt][3])
                             : "r"(addr));
            }
            #pragma unroll
            for (int p = 0; p < 2; p++) {  // Whi fragments
                uint32_t addr = sbase + 2 * TILE_B + sw64(warpN + p * 16 + brow, ks * 2 + bjl);
                asm volatile("ldmatrix.sync.aligned.m8n8.x4.shared.b16 {%0,%1,%2,%3}, [%4];"
                             : "=r"(bf[2 * p][0]), "=r"(bf[2 * p][1]),
                               "=r"(bf[2 * p + 1][0]), "=r"(bf[2 * p + 1][1])
                             : "r"(addr));
            }
            #pragma unroll
            for (int mt = 0; mt < 4; mt++)   // Ahi * Whi
                #pragma unroll
                for (int nt = 0; nt < 4; nt++)
                    asm volatile(
                        "mma.sync.aligned.m16n8k16.row.col.f32.bf16.bf16.f32 "
                        "{%0,%1,%2,%3}, {%4,%5,%6,%7}, {%8,%9}, {%0,%1,%2,%3};"
                        : "+f"(acc[mt][nt][0]), "+f"(acc[mt][nt][1]),
                          "+f"(acc[mt][nt][2]), "+f"(acc[mt][nt][3])
                        : "r"(ahif[mt][0]), "r"(ahif[mt][1]), "r"(ahif[mt][2]), "r"(ahif[mt][3]),
                          "r"(bf[nt][0]), "r"(bf[nt][1]));
            #pragma unroll
            for (int mt = 0; mt < 4; mt++) {
                uint32_t addr = sbase + TILE_B + sw64(warpM + mt * 16 + arow, ks * 2 + ajl);
                asm volatile("ldmatrix.sync.aligned.m8n8.x4.shared.b16 {%0,%1,%2,%3}, [%4];"
                             : "=r"(alof[mt][0]), "=r"(alof[mt][1]), "=r"(alof[mt][2]), "=r"(alof[mt][3])
                             : "r"(addr));
            }
            #pragma unroll
            for (int mt = 0; mt < 4; mt++)   // Alo * Whi
                #pragma unroll
                for (int nt = 0; nt < 4; nt++)
                    asm volatile(
                        "mma.sync.aligned.m16n8k16.row.col.f32.bf16.bf16.f32 "
                        "{%0,%1,%2,%3}, {%4,%5,%6,%7}, {%8,%9}, {%0,%1,%2,%3};"
                        : "+f"(acc[mt][nt][0]), "+f"(acc[mt][nt][1]),
                          "+f"(acc[mt][nt][2]), "+f"(acc[mt][nt][3])
                        : "r"(alof[mt][0]), "r"(alof[mt][1]), "r"(alof[mt][2]), "r"(alof[mt][3]),
                          "r"(bf[nt][0]), "r"(bf[nt][1]));
            #pragma unroll
            for (int p = 0; p < 2; p++) {  // Wlo fragments (reuse bf)
                uint32_t addr = sbase + 3 * TILE_B + sw64(warpN + p * 16 + brow, ks * 2 + bjl);
                asm volatile("ldmatrix.sync.aligned.m8n8.x4.shared.b16 {%0,%1,%2,%3}, [%4];"
                             : "=r"(bf[2 * p][0]), "=r"(bf[2 * p][1]),
                               "=r"(bf[2 * p + 1][0]), "=r"(bf[2 * p + 1][1])
                             : "r"(addr));
            }
            #pragma unroll
            for (int mt = 0; mt < 4; mt++)   // Ahi * Wlo
                #pragma unroll
                for (int nt = 0; nt < 4; nt++)
                    asm volatile(
                        "mma.sync.aligned.m16n8k16.row.col.f32.bf16.bf16.f32 "
                        "{%0,%1,%2,%3}, {%4,%5,%6,%7}, {%8,%9}, {%0,%1,%2,%3};"
                        : "+f"(acc[mt][nt][0]), "+f"(acc[mt][nt][1]),
                          "+f"(acc[mt][nt][2]), "+f"(acc[mt][nt][3])
                        : "r"(ahif[mt][0]), "r"(ahif[mt][1]), "r"(ahif[mt][2]), "r"(ahif[mt][3]),
                          "r"(bf[nt][0]), "r"(bf[nt][1]));
        }
    }

    #pragma unroll
    for (int mt = 0; mt < 4; mt++) {
        int r0 = m0 + warpM + mt * 16 + g;
        #pragma unroll
        for (int nt = 0; nt < 4; nt++) {
            int c0 = n0 + warpN + nt * 8 + 2 * t;
            float v0 = acc[mt][nt][0], v1 = acc[mt][nt][1];
            float v2 = acc[mt][nt][2], v3 = acc[mt][nt][3];
            if (mode == 1) {
                v0 = softplus_f(v0); v1 = softplus_f(v1);
                v2 = softplus_f(v2); v3 = softplus_f(v3);
            } else if (mode == 2) {
                float b0 = __ldg(&bias[c0]), b1 = __ldg(&bias[c0 + 1]);
                v0 = 1.f / (1.f + expf(-(v0 + b0)));
                v1 = 1.f / (1.f + expf(-(v1 + b1)));
                v2 = 1.f / (1.f + expf(-(v2 + b0)));
                v3 = 1.f / (1.f + expf(-(v3 + b1)));
            }
            float2 p0; p0.x = v0; p0.y = v1;
            float2 p1; p1.x = v2; p1.y = v3;
            *(float2*)&C[(size_t)r0 * D_MODEL + c0]       = p0;
            *(float2*)&C[(size_t)(r0 + 8) * D_MODEL + c0] = p1;
        }
    }
}

// ------------- per-(head,chunk) local state S_c = Kf^T V, z_c = sum kf ------
// CHUNK=64: 512 blocks, 32 KB smem, 4x4 register tile per thread
__global__ __launch_bounds__(256) void chunk_state_kernel() {
    extern __shared__ float smf[];
    float* Kc = smf;               // [64][64]
    float* Vc = smf + CHUNK * DH;  // [64][64]
    const int head = blockIdx.x / NCHUNK, chunk = blockIdx.x % NCHUNK;
    const int t0 = chunk * CHUNK, col0 = head * DH;
    const int tid = threadIdx.x;

    for (int i = tid; i < CHUNK * DH / 4; i += 256) {
        int tt = i >> 4, c4 = (i & 15) << 2;
        *(float4*)&Kc[tt * DH + c4] = *(const float4*)&g_kf[(size_t)(t0 + tt) * D_MODEL + col0 + c4];
        *(float4*)&Vc[tt * DH + c4] = *(const float4*)&g_v [(size_t)(t0 + tt) * D_MODEL + col0 + c4];
    }
    __syncthreads();

    const int dt = (tid >> 4) * 4;
    const int et = (tid & 15) * 4;
    float acc[4][4] = {};
    float z[4] = {};
    #pragma unroll 2
    for (int tt = 0; tt < CHUNK; tt++) {
        float4 k4 = *(float4*)&Kc[tt * DH + dt];
        float4 v4 = *(float4*)&Vc[tt * DH + et];
        z[0] += k4.x; z[1] += k4.y; z[2] += k4.z; z[3] += k4.w;
        acc[0][0] = fmaf(k4.x, v4.x, acc[0][0]); acc[0][1] = fmaf(k4.x, v4.y, acc[0][1]);
        acc[0][2] = fmaf(k4.x, v4.z, acc[0][2]); acc[0][3] = fmaf(k4.x, v4.w, acc[0][3]);
        acc[1][0] = fmaf(k4.y, v4.x, acc[1][0]); acc[1][1] = fmaf(k4.y, v4.y, acc[1][1]);
        acc[1][2] = fmaf(k4.y, v4.z, acc[1][2]); acc[1][3] = fmaf(k4.y, v4.w, acc[1][3]);
        acc[2][0] = fmaf(k4.z, v4.x, acc[2][0]); acc[2][1] = fmaf(k4.z, v4.y, acc[2][1]);
        acc[2][2] = fmaf(k4.z, v4.z, acc[2][2]); acc[2][3] = fmaf(k4.z, v4.w, acc[2][3]);
        acc[3][0] = fmaf(k4.w, v4.x, acc[3][0]); acc[3][1] = fmaf(k4.w, v4.y, acc[3][1]);
        acc[3][2] = fmaf(k4.w, v4.z, acc[3][2]); acc[3][3] = fmaf(k4.w, v4.w, acc[3][3]);
    }
    size_t base = (size_t)blockIdx.x * (DH * DH);
    #pragma unroll
    for (int i = 0; i < 4; i++)
        *(float4*)&g_Sc[base + (dt + i) * DH + et] = *(float4*)&acc[i][0];
    if ((tid & 15) == 0) {
        #pragma unroll
        for (int i = 0; i < 4; i++) g_zc[blockIdx.x * DH + dt + i] = z[i];
    }
}

// ------------- sequential prefix over the 32 chunks (per head) --------------
__global__ __launch_bounds__(256) void prefix_kernel(float* __restrict__ out) {
    const int head = blockIdx.x, tid = threadIdx.x;
    float acc[16] = {};
    for (int c = 0; c < NCHUNK; c++) {
        size_t base = ((size_t)head * NCHUNK + c) * (DH * DH);
        #pragma unroll
        for (int k = 0; k < 16; k++) {
            g_Spre[base + tid + k * 256] = acc[k];
            acc[k] += g_Sc[base + tid + k * 256];
        }
    }
    float* kv_out = out + (size_t)T_SEQ * D_MODEL;
    #pragma unroll
    for (int k = 0; k < 16; k++)
        kv_out[(size_t)head * DH * DH + tid + k * 256] = acc[k];

    if (tid < DH) {
        float z = 0.f;
        for (int c = 0; c < NCHUNK; c++) {
            int base = (head * NCHUNK + c) * DH;
            g_zpre[base + tid] = z;
            z += g_zc[base + tid];
        }
        float* z_out = out + (size_t)T_SEQ * D_MODEL + NH * DH * DH;
        z_out[head * DH + tid] = z;
    }
}

// ------------- per-(head,chunk) output, CHUNK=64, 85.5 KB smem --------------
// fuses: qf = softplus(q)*(sigmoid(g)+1e-6) on load; bf16 hi/lo split on store
#define QT_STRIDE 68
#define AS_STRIDE 68
#define CO_SMEM_FLOATS (DH*QT_STRIDE*2 + CHUNK*DH + DH*DH + CHUNK*AS_STRIDE + DH + CHUNK)

__global__ __launch_bounds__(256) void chunk_out_kernel() {
    extern __shared__ float smf[];
    float* Qt  = smf;                       // [64][68]  k-major, gated qf
    float* Kt  = Qt + DH * QT_STRIDE;       // [64][68]
    float* Vs  = Kt + DH * QT_STRIDE;       // [64][64]
    float* Ss  = Vs + CHUNK * DH;           // [64][64]
    float* As  = Ss + DH * DH;              // [64][68]
    float* zs  = As + CHUNK * AS_STRIDE;    // [64]
    float* den = zs + DH;                   // [64]
    const int head = blockIdx.x / NCHUNK, chunk = blockIdx.x % NCHUNK;
    const int t0 = chunk * CHUNK, col0 = head * DH;
    const int tid = threadIdx.x;

    for (int i = tid; i < CHUNK * DH / 4; i += 256) {
        int tt = i >> 4, c4 = (i & 15) << 2;
        float4 q4 = *(const float4*)&g_q[(size_t)(t0 + tt) * D_MODEL + col0 + c4];
        float4 g4 = *(const float4*)&g_g[(size_t)(t0 + tt) * D_MODEL + col0 + c4];
        q4.x *= (g4.x + 1e-6f); q4.y *= (g4.y + 1e-6f);
        q4.z *= (g4.z + 1e-6f); q4.w *= (g4.w + 1e-6f);
        Qt[(c4 + 0) * QT_STRIDE + tt] = q4.x; Qt[(c4 + 1) * QT_STRIDE + tt] = q4.y;
        Qt[(c4 + 2) * QT_STRIDE + tt] = q4.z; Qt[(c4 + 3) * QT_STRIDE + tt] = q4.w;
        float4 k4 = *(const float4*)&g_kf[(size_t)(t0 + tt) * D_MODEL + col0 + c4];
        Kt[(c4 + 0) * QT_STRIDE + tt] = k4.x; Kt[(c4 + 1) * QT_STRIDE + tt] = k4.y;
        Kt[(c4 + 2) * QT_STRIDE + tt] = k4.z; Kt[(c4 + 3) * QT_STRIDE + tt] = k4.w;
        *(float4*)&Vs[tt * DH + c4] = *(const float4*)&g_v[(size_t)(t0 + tt) * D_MODEL + col0 + c4];
    }
    {
        size_t base = ((size_t)head * NCHUNK + chunk) * (DH * DH);
        for (int i = tid; i < DH * DH / 4; i += 256)
            *(float4*)&Ss[i * 4] = *(const float4*)&g_Spre[base + i * 4];
    }
    if (tid < DH)    zs[tid]  = g_zpre[(head * NCHUNK + chunk) * DH + tid];
    if (tid < CHUNK) den[tid] = 0.f;
    __syncthreads();

    // Phase A: A[t][s] = qf_t . kf_s, masked; 256 threads, 4x4 tiles on 64x64
    {
        const int tx = tid & 15, ty = tid >> 4;
        float a[4][4] = {};
        for (int k = 0; k < DH; k++) {
            float qr[4], kr[4];
            *(float4*)&qr[0] = *(float4*)&Qt[k * QT_STRIDE + ty * 4];
            *(float4*)&kr[0] = *(float4*)&Kt[k * QT_STRIDE + tx * 4];
            #pragma unroll
            for (int i = 0; i < 4; i++)
                #pragma unroll
                for (int j = 0; j < 4; j++)
                    a[i][j] = fmaf(qr[i], kr[j], a[i][j]);
        }
        #pragma unroll
        for (int i = 0; i < 4; i++) {
            int tr = ty * 4 + i;
            float rs = 0.f;
            #pragma unroll
            for (int j = 0; j < 4; j++) {
                int s = tx * 4 + j;
                float vv = (s <= tr) ? a[i][j] : 0.f;
                As[tr * AS_STRIDE + s] = vv;
                rs += vv;
            }
            atomicAdd(&den[tr], rs);
        }
    }
    __syncthreads();
    if (tid < CHUNK) {
        float dz = 0.f;
        #pragma unroll 8
        for (int d = 0; d < DH; d++) dz += Qt[d * QT_STRIDE + tid] * zs[d];
        den[tid] += dz + 1e-6f;
    }
    __syncthreads();

    // Phase B: out[t][e] = (qf_t @ Spre + A[t,:] @ V) / den
    // register tile: 2 t-rows x 8 e-cols per thread (32 groups x 8 slots)
    {
        const int es = tid & 7;
        const int tg = tid >> 3;
        const int r0 = tg * 2;
        const int e0 = es * 8;
        float acc[2][8];
        #pragma unroll
        for (int i = 0; i < 2; i++)
            #pragma unroll
            for (int j = 0; j < 8; j++) acc[i][j] = 0.f;

        for (int d = 0; d < DH; d++) {
            float qv[2], sv[8];
            *(float2*)&qv[0] = *(float2*)&Qt[d * QT_STRIDE + r0];
            *(float4*)&sv[0] = *(float4*)&Ss[d * DH + e0];
            *(float4*)&sv[4] = *(float4*)&Ss[d * DH + e0 + 4];
            #pragma unroll
            for (int i = 0; i < 2; i++)
                #pragma unroll
                for (int j = 0; j < 8; j++)
                    acc[i][j] = fmaf(qv[i], sv[j], acc[i][j]);
        }
        for (int s = 0; s < CHUNK; s++) {
            float av[2], vv[8];
            av[0] = As[(r0 + 0) * AS_STRIDE + s];
            av[1] = As[(r0 + 1) * AS_STRIDE + s];
            *(float4*)&vv[0] = *(float4*)&Vs[s * DH + e0];
            *(float4*)&vv[4] = *(float4*)&Vs[s * DH + e0 + 4];
            #pragma unroll
            for (int i = 0; i < 2; i++)
                #pragma unroll
                for (int j = 0; j < 8; j++)
                    acc[i][j] = fmaf(av[i], vv[j], acc[i][j]);
        }
        #pragma unroll
        for (int i = 0; i < 2; i++) {
            int tr = r0 + i;
            float dinv = 1.f / den[tr];
            size_t obase = ((size_t)(t0 + tr) * D_MODEL + col0 + e0) >> 1;  // bf162 idx
            #pragma unroll
            for (int jj = 0; jj < 4; jj++) {
                float o0 = acc[i][jj * 2 + 0] * dinv;
                float o1 = acc[i][jj * 2 + 1] * dinv;
                __nv_bfloat16 h0 = __float2bfloat16_rn(o0);
                __nv_bfloat16 h1 = __float2bfloat16_rn(o1);
                __nv_bfloat162 H; H.x = h0; H.y = h1;
                __nv_bfloat162 L;
                L.x = __float2bfloat16_rn(o0 - __bfloat162float(h0));
                L.y = __float2bfloat16_rn(o1 - __bfloat162float(h1));
                ((__nv_bfloat162*)g_athi)[obase + jj] = H;
                ((__nv_bfloat162*)g_atlo)[obase + jj] = L;
            }
        }
    }
}

// ---------------------------------------------------------------------------
extern "C" void kernel_launch(void* const* d_in, const int* in_sizes, int n_in,
                              void* d_out, int out_size)
{
    const float* x  = (const float*)d_in[0];
    const float* Wq = (const float*)d_in[1];
    const float* Wk = (const float*)d_in[2];
    const float* Wv = (const float*)d_in[3];
    const float* Wo = (const float*)d_in[4];
    const float* Wg = (const float*)d_in[5];
    const float* bg = (const float*)d_in[6];
    float* out = (float*)d_out;

    float *qb, *gb, *kb, *vb;
    cudaGetSymbolAddress((void**)&qb, g_q);
    cudaGetSymbolAddress((void**)&gb, g_g);
    cudaGetSymbolAddress((void**)&kb, g_kf);
    cudaGetSymbolAddress((void**)&vb, g_v);
    __nv_bfloat16 *xhi, *xlo, *whi, *wlo, *athi, *atlo;
    cudaGetSymbolAddress((void**)&xhi, g_xhi);
    cudaGetSymbolAddress((void**)&xlo, g_xlo);
    cudaGetSymbolAddress((void**)&whi, g_Whi);
    cudaGetSymbolAddress((void**)&wlo, g_Wlo);
    cudaGetSymbolAddress((void**)&athi, g_athi);
    cudaGetSymbolAddress((void**)&atlo, g_atlo);

    const int cs_smem = CHUNK * DH * 2 * sizeof(float);
    const int co_smem = CO_SMEM_FLOATS * sizeof(float);
    const int gm_smem = NST * STAGE_B;
    cudaFuncSetAttribute(chunk_state_kernel, cudaFuncAttributeMaxDynamicSharedMemorySize, cs_smem);
    cudaFuncSetAttribute(chunk_out_kernel,   cudaFuncAttributeMaxDynamicSharedMemorySize, co_smem);
    cudaFuncSetAttribute(mma_gemm_kernel,    cudaFuncAttributeMaxDynamicSharedMemorySize, gm_smem);

    // launches 0..2: splits (QKVG GEMM lands at launch idx 3 = ncu capture)
    split_kernel<<<T_SEQ * D_MODEL / 1024, 256>>>(x, xhi, xlo, T_SEQ * D_MODEL / 4);
    {
        dim3 grid(D_MODEL * D_MODEL / 1024, 4);
        split4w_kernel<<<grid, 256>>>(Wq, Wk, Wv, Wg);
    }
    split_kernel<<<D_MODEL * D_MODEL / 1024, 256>>>(
        Wo, whi + (size_t)4 * D_MODEL * D_MODEL, wlo + (size_t)4 * D_MODEL * D_MODEL,
        D_MODEL * D_MODEL / 4);

    // launch 3: fused Q/K/V/G projections (profiled)
    {
        dim3 grid(D_MODEL / 128, T_SEQ / 128, 4);
        mma_gemm_kernel<<<grid, 256, gm_smem>>>(xhi, xlo, bg, qb, kb, vb, gb, 0);
    }
    chunk_state_kernel<<<NH * NCHUNK, 256, cs_smem>>>();
    prefix_kernel<<<NH, 256>>>(out);
    chunk_out_kernel<<<NH * NCHUNK, 256, co_smem>>>();
    {
        dim3 grid(D_MODEL / 128, T_SEQ / 128, 1);
        mma_gemm_kernel<<<grid, 256, gm_smem>>>(athi, atlo, nullptr, out, out, out, out, 4);
    }
}

// round 14
// speedup vs baseline: 1.0439x; 1.0439x over previous
#include <cuda_runtime.h>
#include <cuda_bf16.h>
#include <math.h>
#include <stdint.h>

#define T_SEQ   2048
#define D_MODEL 1024
#define NH      16
#define DH      64
#define CHUNK   128
#define NCHUNK  (T_SEQ / CHUNK)   // 16
#define KT      32                // K elems per tile chunk (64B rows)
#define NKC     (D_MODEL / KT)    // 32 mainloop iterations
#define TILE_B  8192              // 128 rows * 64B
#define STAGE_B 32768             // Ahi, Alo, Whi, Wlo tiles
#define NST     3

// ---------------- scratch (static __device__ arrays; no allocation) ----------
__device__ __align__(256) float g_q  [T_SEQ * D_MODEL];
__device__ __align__(256) float g_g  [T_SEQ * D_MODEL];
__device__ __align__(256) float g_kf [T_SEQ * D_MODEL];
__device__ __align__(256) float g_v  [T_SEQ * D_MODEL];
__device__ __align__(256) float g_Sc  [NH * NCHUNK * DH * DH];
__device__ __align__(256) float g_Spre[NH * NCHUNK * DH * DH];
__device__ __align__(256) float g_zc  [NH * NCHUNK * DH];
__device__ __align__(256) float g_zpre[NH * NCHUNK * DH];
__device__ __align__(256) __nv_bfloat16 g_xhi [T_SEQ * D_MODEL];
__device__ __align__(256) __nv_bfloat16 g_xlo [T_SEQ * D_MODEL];
__device__ __align__(256) __nv_bfloat16 g_Whi [5 * D_MODEL * D_MODEL];
__device__ __align__(256) __nv_bfloat16 g_Wlo [5 * D_MODEL * D_MODEL];
__device__ __align__(256) __nv_bfloat16 g_athi[T_SEQ * D_MODEL];
__device__ __align__(256) __nv_bfloat16 g_atlo[T_SEQ * D_MODEL];

__device__ __forceinline__ float softplus_f(float x) {
    return (x > 20.f) ? x : log1pf(expf(x));
}

__device__ __forceinline__ void split4(float4 v, __nv_bfloat162* hi2, __nv_bfloat162* lo2) {
    __nv_bfloat16 h0 = __float2bfloat16_rn(v.x), h1 = __float2bfloat16_rn(v.y);
    __nv_bfloat16 h2 = __float2bfloat16_rn(v.z), h3 = __float2bfloat16_rn(v.w);
    hi2[0].x = h0; hi2[0].y = h1; hi2[1].x = h2; hi2[1].y = h3;
    lo2[0].x = __float2bfloat16_rn(v.x - __bfloat162float(h0));
    lo2[0].y = __float2bfloat16_rn(v.y - __bfloat162float(h1));
    lo2[1].x = __float2bfloat16_rn(v.z - __bfloat162float(h2));
    lo2[1].y = __float2bfloat16_rn(v.w - __bfloat162float(h3));
}

// =============== split kernels: fp32 -> (hi, lo) bf16 =======================
__global__ __launch_bounds__(256) void split_kernel(const float* __restrict__ src,
                                                    __nv_bfloat16* __restrict__ hi,
                                                    __nv_bfloat16* __restrict__ lo, int n4) {
    int i = blockIdx.x * 256 + threadIdx.x;
    if (i >= n4) return;
    __nv_bfloat162 H[2], L[2];
    split4(((const float4*)src)[i], H, L);
    ((__nv_bfloat162*)hi)[i * 2 + 0] = H[0];
    ((__nv_bfloat162*)hi)[i * 2 + 1] = H[1];
    ((__nv_bfloat162*)lo)[i * 2 + 0] = L[0];
    ((__nv_bfloat162*)lo)[i * 2 + 1] = L[1];
}

__global__ __launch_bounds__(256) void split4w_kernel(
    const float* __restrict__ s0, const float* __restrict__ s1,
    const float* __restrict__ s2, const float* __restrict__ s3)
{
    const float* srcs[4] = {s0, s1, s2, s3};
    int z = blockIdx.y;
    int i = blockIdx.x * 256 + threadIdx.x;
    size_t off = (size_t)z * (D_MODEL * D_MODEL / 4);
    __nv_bfloat162 H[2], L[2];
    split4(((const float4*)srcs[z])[i], H, L);
    ((__nv_bfloat162*)g_Whi)[(off + i) * 2 + 0] = H[0];
    ((__nv_bfloat162*)g_Whi)[(off + i) * 2 + 1] = H[1];
    ((__nv_bfloat162*)g_Wlo)[(off + i) * 2 + 0] = L[0];
    ((__nv_bfloat162*)g_Wlo)[(off + i) * 2 + 1] = L[1];
}

// ======== fused 3-term split-bf16 GEMM: C = A * W^T + activation ============
// All four fragment groups hoisted per ks (separate regs, ~120 live):
// only mma block 1 waits on LDSM; blocks 2/3 operands land under block 1.
__device__ __forceinline__ uint32_t sw64(int row, int j) {
    return (uint32_t)(row * 64 + 16 * (j ^ ((row >> 1) & 3)));
}

__global__ __launch_bounds__(256, 2) void mma_gemm_kernel(
    const __nv_bfloat16* __restrict__ Ahi, const __nv_bfloat16* __restrict__ Alo,
    const float* __restrict__ bias,
    float* C0, float* C1, float* C2, float* C3, int wbase)
{
    extern __shared__ __nv_bfloat16 sm[];
    const int tid = threadIdx.x, lane = tid & 31, wid = tid >> 5;
    const int g = lane >> 2, t = lane & 3;
    const int warpM = (wid & 1) * 64, warpN = (wid >> 1) * 32;
    const int z = blockIdx.z, widx = wbase + z;
    const int m0 = blockIdx.y * 128, n0 = blockIdx.x * 128;

    const __nv_bfloat16* Wh = g_Whi + (size_t)widx * D_MODEL * D_MODEL;
    const __nv_bfloat16* Wl = g_Wlo + (size_t)widx * D_MODEL * D_MODEL;
    float* Cs[4] = {C0, C1, C2, C3};
    float* C = Cs[z];
    const int mode = (widx <= 1) ? 1 : (widx == 3 ? 2 : 0);

    float acc[4][4][4];
    #pragma unroll
    for (int a = 0; a < 4; a++)
        #pragma unroll
        for (int b = 0; b < 4; b++)
            #pragma unroll
            for (int c = 0; c < 4; c++) acc[a][b][c] = 0.f;

    const uint32_t smb = (uint32_t)__cvta_generic_to_shared(sm);
    const int arow = (lane & 7) + ((lane >> 3) & 1) * 8;
    const int ajl  = lane >> 4;
    const int bsel = lane >> 3;
    const int brow = (lane & 7) + ((bsel >> 1) & 1) * 8;
    const int bjl  = bsel & 1;

    auto issue = [&](int kc) {
        const uint32_t sbase = smb + (kc % NST) * STAGE_B;
        #pragma unroll
        for (int r = 0; r < 2; r++) {
            int id = tid + r * 256, row = id >> 2, c = id & 3;
            uint32_t off = sw64(row, c);
            size_t ga = (size_t)(m0 + row) * D_MODEL + kc * KT + c * 8;
            size_t gb = (size_t)(n0 + row) * D_MODEL + kc * KT + c * 8;
            asm volatile("cp.async.cg.shared.global [%0], [%1], 16;" :: "r"(sbase + off),              "l"((const void*)(Ahi + ga)));
            asm volatile("cp.async.cg.shared.global [%0], [%1], 16;" :: "r"(sbase + TILE_B + off),     "l"((const void*)(Alo + ga)));
            asm volatile("cp.async.cg.shared.global [%0], [%1], 16;" :: "r"(sbase + 2 * TILE_B + off), "l"((const void*)(Wh + gb)));
            asm volatile("cp.async.cg.shared.global [%0], [%1], 16;" :: "r"(sbase + 3 * TILE_B + off), "l"((const void*)(Wl + gb)));
        }
        asm volatile("cp.async.commit_group;" ::: "memory");
    };

    issue(0); issue(1);

    for (int it = 0; it < NKC; it++) {
        if (it < NKC - 1) asm volatile("cp.async.wait_group 1;" ::: "memory");
        else              asm volatile("cp.async.wait_group 0;" ::: "memory");
        __syncthreads();
        if (it + 2 < NKC) issue(it + 2);

        const uint32_t sbase = smb + (it % NST) * STAGE_B;
        #pragma unroll
        for (int ks = 0; ks < 2; ks++) {
            uint32_t ahif[4][4], alof[4][4], bfh[4][2], bfl[4][2];
            // ---- hoist ALL fragment loads: block1 hides latency of 2/3 -----
            #pragma unroll
            for (int mt = 0; mt < 4; mt++) {
                uint32_t addr = sbase + sw64(warpM + mt * 16 + arow, ks * 2 + ajl);
                asm volatile("ldmatrix.sync.aligned.m8n8.x4.shared.b16 {%0,%1,%2,%3}, [%4];"
                             : "=r"(ahif[mt][0]), "=r"(ahif[mt][1]), "=r"(ahif[mt][2]), "=r"(ahif[mt][3])
                             : "r"(addr));
            }
            #pragma unroll
            for (int p = 0; p < 2; p++) {
                uint32_t addr = sbase + 2 * TILE_B + sw64(warpN + p * 16 + brow, ks * 2 + bjl);
                asm volatile("ldmatrix.sync.aligned.m8n8.x4.shared.b16 {%0,%1,%2,%3}, [%4];"
                             : "=r"(bfh[2 * p][0]), "=r"(bfh[2 * p][1]),
                               "=r"(bfh[2 * p + 1][0]), "=r"(bfh[2 * p + 1][1])
                             : "r"(addr));
            }
            #pragma unroll
            for (int mt = 0; mt < 4; mt++) {
                uint32_t addr = sbase + TILE_B + sw64(warpM + mt * 16 + arow, ks * 2 + ajl);
                asm volatile("ldmatrix.sync.aligned.m8n8.x4.shared.b16 {%0,%1,%2,%3}, [%4];"
                             : "=r"(alof[mt][0]), "=r"(alof[mt][1]), "=r"(alof[mt][2]), "=r"(alof[mt][3])
                             : "r"(addr));
            }
            #pragma unroll
            for (int p = 0; p < 2; p++) {
                uint32_t addr = sbase + 3 * TILE_B + sw64(warpN + p * 16 + brow, ks * 2 + bjl);
                asm volatile("ldmatrix.sync.aligned.m8n8.x4.shared.b16 {%0,%1,%2,%3}, [%4];"
                             : "=r"(bfl[2 * p][0]), "=r"(bfl[2 * p][1]),
                               "=r"(bfl[2 * p + 1][0]), "=r"(bfl[2 * p + 1][1])
                             : "r"(addr));
            }
            #pragma unroll
            for (int mt = 0; mt < 4; mt++)   // Ahi * Whi
                #pragma unroll
                for (int nt = 0; nt < 4; nt++)
                    asm volatile(
                        "mma.sync.aligned.m16n8k16.row.col.f32.bf16.bf16.f32 "
                        "{%0,%1,%2,%3}, {%4,%5,%6,%7}, {%8,%9}, {%0,%1,%2,%3};"
                        : "+f"(acc[mt][nt][0]), "+f"(acc[mt][nt][1]),
                          "+f"(acc[mt][nt][2]), "+f"(acc[mt][nt][3])
                        : "r"(ahif[mt][0]), "r"(ahif[mt][1]), "r"(ahif[mt][2]), "r"(ahif[mt][3]),
                          "r"(bfh[nt][0]), "r"(bfh[nt][1]));
            #pragma unroll
            for (int mt = 0; mt < 4; mt++)   // Alo * Whi
                #pragma unroll
                for (int nt = 0; nt < 4; nt++)
                    asm volatile(
                        "mma.sync.aligned.m16n8k16.row.col.f32.bf16.bf16.f32 "
                        "{%0,%1,%2,%3}, {%4,%5,%6,%7}, {%8,%9}, {%0,%1,%2,%3};"
                        : "+f"(acc[mt][nt][0]), "+f"(acc[mt][nt][1]),
                          "+f"(acc[mt][nt][2]), "+f"(acc[mt][nt][3])
                        : "r"(alof[mt][0]), "r"(alof[mt][1]), "r"(alof[mt][2]), "r"(alof[mt][3]),
                          "r"(bfh[nt][0]), "r"(bfh[nt][1]));
            #pragma unroll
            for (int mt = 0; mt < 4; mt++)   // Ahi * Wlo
                #pragma unroll
                for (int nt = 0; nt < 4; nt++)
                    asm volatile(
                        "mma.sync.aligned.m16n8k16.row.col.f32.bf16.bf16.f32 "
                        "{%0,%1,%2,%3}, {%4,%5,%6,%7}, {%8,%9}, {%0,%1,%2,%3};"
                        : "+f"(acc[mt][nt][0]), "+f"(acc[mt][nt][1]),
                          "+f"(acc[mt][nt][2]), "+f"(acc[mt][nt][3])
                        : "r"(ahif[mt][0]), "r"(ahif[mt][1]), "r"(ahif[mt][2]), "r"(ahif[mt][3]),
                          "r"(bfl[nt][0]), "r"(bfl[nt][1]));
        }
    }

    #pragma unroll
    for (int mt = 0; mt < 4; mt++) {
        int r0 = m0 + warpM + mt * 16 + g;
        #pragma unroll
        for (int nt = 0; nt < 4; nt++) {
            int c0 = n0 + warpN + nt * 8 + 2 * t;
            float v0 = acc[mt][nt][0], v1 = acc[mt][nt][1];
            float v2 = acc[mt][nt][2], v3 = acc[mt][nt][3];
            if (mode == 1) {
                v0 = softplus_f(v0); v1 = softplus_f(v1);
                v2 = softplus_f(v2); v3 = softplus_f(v3);
            } else if (mode == 2) {
                float b0 = __ldg(&bias[c0]), b1 = __ldg(&bias[c0 + 1]);
                v0 = 1.f / (1.f + expf(-(v0 + b0)));
                v1 = 1.f / (1.f + expf(-(v1 + b1)));
                v2 = 1.f / (1.f + expf(-(v2 + b0)));
                v3 = 1.f / (1.f + expf(-(v3 + b1)));
            }
            float2 p0; p0.x = v0; p0.y = v1;
            float2 p1; p1.x = v2; p1.y = v3;
            *(float2*)&C[(size_t)r0 * D_MODEL + c0]       = p0;
            *(float2*)&C[(size_t)(r0 + 8) * D_MODEL + c0] = p1;
        }
    }
}

// ------------- per-(head,chunk) local state S_c = Kf^T V, z_c = sum kf ------
__global__ __launch_bounds__(256) void chunk_state_kernel() {
    extern __shared__ float smf[];
    float* Kc = smf;
    float* Vc = smf + CHUNK * DH;
    const int head = blockIdx.x >> 4, chunk = blockIdx.x & 15;
    const int t0 = chunk * CHUNK, col0 = head * DH;
    const int tid = threadIdx.x;

    for (int i = tid; i < CHUNK * DH / 4; i += 256) {
        int tt = i >> 4, c4 = (i & 15) << 2;
        *(float4*)&Kc[tt * DH + c4] = *(const float4*)&g_kf[(size_t)(t0 + tt) * D_MODEL + col0 + c4];
        *(float4*)&Vc[tt * DH + c4] = *(const float4*)&g_v [(size_t)(t0 + tt) * D_MODEL + col0 + c4];
    }
    __syncthreads();

    const int dt = (tid >> 4) * 4;
    const int et = (tid & 15) * 4;
    float acc[4][4] = {};
    float z[4] = {};
    #pragma unroll 2
    for (int tt = 0; tt < CHUNK; tt++) {
        float4 k4 = *(float4*)&Kc[tt * DH + dt];
        float4 v4 = *(float4*)&Vc[tt * DH + et];
        z[0] += k4.x; z[1] += k4.y; z[2] += k4.z; z[3] += k4.w;
        acc[0][0] = fmaf(k4.x, v4.x, acc[0][0]); acc[0][1] = fmaf(k4.x, v4.y, acc[0][1]);
        acc[0][2] = fmaf(k4.x, v4.z, acc[0][2]); acc[0][3] = fmaf(k4.x, v4.w, acc[0][3]);
        acc[1][0] = fmaf(k4.y, v4.x, acc[1][0]); acc[1][1] = fmaf(k4.y, v4.y, acc[1][1]);
        acc[1][2] = fmaf(k4.y, v4.z, acc[1][2]); acc[1][3] = fmaf(k4.y, v4.w, acc[1][3]);
        acc[2][0] = fmaf(k4.z, v4.x, acc[2][0]); acc[2][1] = fmaf(k4.z, v4.y, acc[2][1]);
        acc[2][2] = fmaf(k4.z, v4.z, acc[2][2]); acc[2][3] = fmaf(k4.z, v4.w, acc[2][3]);
        acc[3][0] = fmaf(k4.w, v4.x, acc[3][0]); acc[3][1] = fmaf(k4.w, v4.y, acc[3][1]);
        acc[3][2] = fmaf(k4.w, v4.z, acc[3][2]); acc[3][3] = fmaf(k4.w, v4.w, acc[3][3]);
    }
    size_t base = (size_t)blockIdx.x * (DH * DH);
    #pragma unroll
    for (int i = 0; i < 4; i++)
        *(float4*)&g_Sc[base + (dt + i) * DH + et] = *(float4*)&acc[i][0];
    if ((tid & 15) == 0) {
        #pragma unroll
        for (int i = 0; i < 4; i++) g_zc[blockIdx.x * DH + dt + i] = z[i];
    }
}

// ------------- sequential prefix over the 16 chunks (per head) --------------
__global__ __launch_bounds__(256) void prefix_kernel(float* __restrict__ out) {
    const int head = blockIdx.x, tid = threadIdx.x;
    float acc[16] = {};
    for (int c = 0; c < NCHUNK; c++) {
        size_t base = ((size_t)head * NCHUNK + c) * (DH * DH);
        #pragma unroll
        for (int k = 0; k < 16; k++) {
            g_Spre[base + tid + k * 256] = acc[k];
            acc[k] += g_Sc[base + tid + k * 256];
        }
    }
    float* kv_out = out + (size_t)T_SEQ * D_MODEL;
    #pragma unroll
    for (int k = 0; k < 16; k++)
        kv_out[(size_t)head * DH * DH + tid + k * 256] = acc[k];

    if (tid < DH) {
        float z = 0.f;
        for (int c = 0; c < NCHUNK; c++) {
            int base = (head * NCHUNK + c) * DH;
            g_zpre[base + tid] = z;
            z += g_zc[base + tid];
        }
        float* z_out = out + (size_t)T_SEQ * D_MODEL + NH * DH * DH;
        z_out[head * DH + tid] = z;
    }
}

// ------------- per-(head,chunk) output, 256 threads (round-11 state) --------
#define QT_STRIDE 132
#define AS_STRIDE 132
#define CO_SMEM_FLOATS (DH*QT_STRIDE*2 + CHUNK*DH + DH*DH + CHUNK*AS_STRIDE + DH + CHUNK)

__global__ __launch_bounds__(256) void chunk_out_kernel() {
    extern __shared__ float smf[];
    float* Qt  = smf;
    float* Kt  = Qt + DH * QT_STRIDE;
    float* Vs  = Kt + DH * QT_STRIDE;
    float* Ss  = Vs + CHUNK * DH;
    float* As  = Ss + DH * DH;
    float* zs  = As + CHUNK * AS_STRIDE;
    float* den = zs + DH;
    const int head = blockIdx.x >> 4, chunk = blockIdx.x & 15;
    const int t0 = chunk * CHUNK, col0 = head * DH;
    const int tid = threadIdx.x;

    for (int i = tid; i < CHUNK * DH / 4; i += 256) {
        int tt = i >> 4, c4 = (i & 15) << 2;
        float4 q4 = *(const float4*)&g_q[(size_t)(t0 + tt) * D_MODEL + col0 + c4];
        float4 g4 = *(const float4*)&g_g[(size_t)(t0 + tt) * D_MODEL + col0 + c4];
        q4.x *= (g4.x + 1e-6f); q4.y *= (g4.y + 1e-6f);
        q4.z *= (g4.z + 1e-6f); q4.w *= (g4.w + 1e-6f);
        Qt[(c4 + 0) * QT_STRIDE + tt] = q4.x; Qt[(c4 + 1) * QT_STRIDE + tt] = q4.y;
        Qt[(c4 + 2) * QT_STRIDE + tt] = q4.z; Qt[(c4 + 3) * QT_STRIDE + tt] = q4.w;
        float4 k4 = *(const float4*)&g_kf[(size_t)(t0 + tt) * D_MODEL + col0 + c4];
        Kt[(c4 + 0) * QT_STRIDE + tt] = k4.x; Kt[(c4 + 1) * QT_STRIDE + tt] = k4.y;
        Kt[(c4 + 2) * QT_STRIDE + tt] = k4.z; Kt[(c4 + 3) * QT_STRIDE + tt] = k4.w;
        *(float4*)&Vs[tt * DH + c4] = *(const float4*)&g_v[(size_t)(t0 + tt) * D_MODEL + col0 + c4];
    }
    {
        size_t base = ((size_t)head * NCHUNK + chunk) * (DH * DH);
        for (int i = tid; i < DH * DH / 4; i += 256)
            *(float4*)&Ss[i * 4] = *(const float4*)&g_Spre[base + i * 4];
    }
    if (tid < DH)    zs[tid]  = g_zpre[(head * NCHUNK + chunk) * DH + tid];
    if (tid < CHUNK) den[tid] = 0.f;
    __syncthreads();

    // Phase A: A[t][s] = qf_t . kf_s, masked; 256 threads, 8x8 tiles
    {
        const int tx = tid & 15, ty = tid >> 4;
        float a[8][8] = {};
        for (int k = 0; k < DH; k++) {
            float qr[8], kr[8];
            *(float4*)&qr[0] = *(float4*)&Qt[k * QT_STRIDE + ty * 8];
            *(float4*)&qr[4] = *(float4*)&Qt[k * QT_STRIDE + ty * 8 + 4];
            *(float4*)&kr[0] = *(float4*)&Kt[k * QT_STRIDE + tx * 8];
            *(float4*)&kr[4] = *(float4*)&Kt[k * QT_STRIDE + tx * 8 + 4];
            #pragma unroll
            for (int i = 0; i < 8; i++)
                #pragma unroll
                for (int j = 0; j < 8; j++)
                    a[i][j] = fmaf(qr[i], kr[j], a[i][j]);
        }
        #pragma unroll
        for (int i = 0; i < 8; i++) {
            int tr = ty * 8 + i;
            float rs = 0.f;
            #pragma unroll
            for (int j = 0; j < 8; j++) {
                int s = tx * 8 + j;
                float vv = (s <= tr) ? a[i][j] : 0.f;
                As[tr * AS_STRIDE + s] = vv;
                rs += vv;
            }
            atomicAdd(&den[tr], rs);
        }
    }
    __syncthreads();
    if (tid < CHUNK) {
        float dz = 0.f;
        #pragma unroll 8
        for (int d = 0; d < DH; d++) dz += Qt[d * QT_STRIDE + tid] * zs[d];
        den[tid] += dz + 1e-6f;
    }
    __syncthreads();

    // Phase B: register tile 4 t-rows x 8 e-cols per thread
    {
        const int es = tid & 7;
        const int tg = tid >> 3;
        const int r0 = tg * 4;
        const int e0 = es * 8;
        float acc[4][8];
        #pragma unroll
        for (int i = 0; i < 4; i++)
            #pragma unroll
            for (int j = 0; j < 8; j++) acc[i][j] = 0.f;

        for (int d = 0; d < DH; d++) {
            float qv[4], sv[8];
            *(float4*)&qv[0] = *(float4*)&Qt[d * QT_STRIDE + r0];
            *(float4*)&sv[0] = *(float4*)&Ss[d * DH + e0];
            *(float4*)&sv[4] = *(float4*)&Ss[d * DH + e0 + 4];
            #pragma unroll
            for (int i = 0; i < 4; i++)
                #pragma unroll
                for (int j = 0; j < 8; j++)
                    acc[i][j] = fmaf(qv[i], sv[j], acc[i][j]);
        }
        for (int s = 0; s < CHUNK; s++) {
            float av[4], vv[8];
            av[0] = As[(r0 + 0) * AS_STRIDE + s];
            av[1] = As[(r0 + 1) * AS_STRIDE + s];
            av[2] = As[(r0 + 2) * AS_STRIDE + s];
            av[3] = As[(r0 + 3) * AS_STRIDE + s];
            *(float4*)&vv[0] = *(float4*)&Vs[s * DH + e0];
            *(float4*)&vv[4] = *(float4*)&Vs[s * DH + e0 + 4];
            #pragma unroll
            for (int i = 0; i < 4; i++)
                #pragma unroll
                for (int j = 0; j < 8; j++)
                    acc[i][j] = fmaf(av[i], vv[j], acc[i][j]);
        }
        #pragma unroll
        for (int i = 0; i < 4; i++) {
            int tr = r0 + i;
            float dinv = 1.f / den[tr];
            size_t obase = ((size_t)(t0 + tr) * D_MODEL + col0 + e0) >> 1;  // bf162 idx
            #pragma unroll
            for (int jj = 0; jj < 4; jj++) {
                float o0 = acc[i][jj * 2 + 0] * dinv;
                float o1 = acc[i][jj * 2 + 1] * dinv;
                __nv_bfloat16 h0 = __float2bfloat16_rn(o0);
                __nv_bfloat16 h1 = __float2bfloat16_rn(o1);
                __nv_bfloat162 H; H.x = h0; H.y = h1;
                __nv_bfloat162 L;
                L.x = __float2bfloat16_rn(o0 - __bfloat162float(h0));
                L.y = __float2bfloat16_rn(o1 - __bfloat162float(h1));
                ((__nv_bfloat162*)g_athi)[obase + jj] = H;
                ((__nv_bfloat162*)g_atlo)[obase + jj] = L;
            }
        }
    }
}

// ---------------------------------------------------------------------------
extern "C" void kernel_launch(void* const* d_in, const int* in_sizes, int n_in,
                              void* d_out, int out_size)
{
    const float* x  = (const float*)d_in[0];
    const float* Wq = (const float*)d_in[1];
    const float* Wk = (const float*)d_in[2];
    const float* Wv = (const float*)d_in[3];
    const float* Wo = (const float*)d_in[4];
    const float* Wg = (const float*)d_in[5];
    const float* bg = (const float*)d_in[6];
    float* out = (float*)d_out;

    float *qb, *gb, *kb, *vb;
    cudaGetSymbolAddress((void**)&qb, g_q);
    cudaGetSymbolAddress((void**)&gb, g_g);
    cudaGetSymbolAddress((void**)&kb, g_kf);
    cudaGetSymbolAddress((void**)&vb, g_v);
    __nv_bfloat16 *xhi, *xlo, *whi, *wlo, *athi, *atlo;
    cudaGetSymbolAddress((void**)&xhi, g_xhi);
    cudaGetSymbolAddress((void**)&xlo, g_xlo);
    cudaGetSymbolAddress((void**)&whi, g_Whi);
    cudaGetSymbolAddress((void**)&wlo, g_Wlo);
    cudaGetSymbolAddress((void**)&athi, g_athi);
    cudaGetSymbolAddress((void**)&atlo, g_atlo);

    const int cs_smem = CHUNK * DH * 2 * sizeof(float);
    const int co_smem = CO_SMEM_FLOATS * sizeof(float);
    const int gm_smem = NST * STAGE_B;
    cudaFuncSetAttribute(chunk_state_kernel, cudaFuncAttributeMaxDynamicSharedMemorySize, cs_smem);
    cudaFuncSetAttribute(chunk_out_kernel,   cudaFuncAttributeMaxDynamicSharedMemorySize, co_smem);
    cudaFuncSetAttribute(mma_gemm_kernel,    cudaFuncAttributeMaxDynamicSharedMemorySize, gm_smem);

    // launches 0..2: splits (QKVG GEMM lands at launch idx 3 = ncu capture)
    split_kernel<<<T_SEQ * D_MODEL / 1024, 256>>>(x, xhi, xlo, T_SEQ * D_MODEL / 4);
    {
        dim3 grid(D_MODEL * D_MODEL / 1024, 4);
        split4w_kernel<<<grid, 256>>>(Wq, Wk, Wv, Wg);
    }
    split_kernel<<<D_MODEL * D_MODEL / 1024, 256>>>(
        Wo, whi + (size_t)4 * D_MODEL * D_MODEL, wlo + (size_t)4 * D_MODEL * D_MODEL,
        D_MODEL * D_MODEL / 4);

    // launch 3: fused Q/K/V/G projections (profiled)
    {
        dim3 grid(D_MODEL / 128, T_SEQ / 128, 4);
        mma_gemm_kernel<<<grid, 256, gm_smem>>>(xhi, xlo, bg, qb, kb, vb, gb, 0);
    }
    chunk_state_kernel<<<NH * NCHUNK, 256, cs_smem>>>();
    prefix_kernel<<<NH, 256>>>(out);
    chunk_out_kernel<<<NH * NCHUNK, 256, co_smem>>>();
    {
        dim3 grid(D_MODEL / 128, T_SEQ / 128, 1);
        mma_gemm_kernel<<<grid, 256, gm_smem>>>(athi, atlo, nullptr, out, out, out, out, 4);
    }
}

// round 15
// speedup vs baseline: 1.0767x; 1.0314x over previous
#include <cuda_runtime.h>
#include <cuda_bf16.h>
#include <math.h>
#include <stdint.h>

#define T_SEQ   2048
#define D_MODEL 1024
#define NH      16
#define DH      64
#define CHUNK   128
#define NCHUNK  (T_SEQ / CHUNK)   // 16
#define KT      32
#define NKC     (D_MODEL / KT)    // 32
#define TILE_B  8192
#define STAGE_B 32768
#define NST     3

// ---------------- scratch (static __device__ arrays; no allocation) ----------
__device__ __align__(256) float g_q  [T_SEQ * D_MODEL];
__device__ __align__(256) float g_g  [T_SEQ * D_MODEL];
__device__ __align__(256) float g_kf [T_SEQ * D_MODEL];
__device__ __align__(256) float g_v  [T_SEQ * D_MODEL];
__device__ __align__(256) float g_Sc  [NH * NCHUNK * DH * DH];
__device__ __align__(256) float g_Spre[NH * NCHUNK * DH * DH];
__device__ __align__(256) float g_zc  [NH * NCHUNK * DH];
__device__ __align__(256) float g_zpre[NH * NCHUNK * DH];
__device__ __align__(256) float g_As [NH * NCHUNK * CHUNK * CHUNK];  // 16.8 MB
__device__ __align__(256) float g_P  [NH * NCHUNK * CHUNK * DH];     // 8.4 MB
__device__ __align__(256) float g_den[NH * NCHUNK * CHUNK];
__device__ __align__(256) __nv_bfloat16 g_xhi [T_SEQ * D_MODEL];
__device__ __align__(256) __nv_bfloat16 g_xlo [T_SEQ * D_MODEL];
__device__ __align__(256) __nv_bfloat16 g_Whi [5 * D_MODEL * D_MODEL];
__device__ __align__(256) __nv_bfloat16 g_Wlo [5 * D_MODEL * D_MODEL];
__device__ __align__(256) __nv_bfloat16 g_athi[T_SEQ * D_MODEL];
__device__ __align__(256) __nv_bfloat16 g_atlo[T_SEQ * D_MODEL];

__device__ __forceinline__ float softplus_f(float x) {
    return (x > 20.f) ? x : log1pf(expf(x));
}

__device__ __forceinline__ void split4(float4 v, __nv_bfloat162* hi2, __nv_bfloat162* lo2) {
    __nv_bfloat16 h0 = __float2bfloat16_rn(v.x), h1 = __float2bfloat16_rn(v.y);
    __nv_bfloat16 h2 = __float2bfloat16_rn(v.z), h3 = __float2bfloat16_rn(v.w);
    hi2[0].x = h0; hi2[0].y = h1; hi2[1].x = h2; hi2[1].y = h3;
    lo2[0].x = __float2bfloat16_rn(v.x - __bfloat162float(h0));
    lo2[0].y = __float2bfloat16_rn(v.y - __bfloat162float(h1));
    lo2[1].x = __float2bfloat16_rn(v.z - __bfloat162float(h2));
    lo2[1].y = __float2bfloat16_rn(v.w - __bfloat162float(h3));
}

// =========== one-launch split: 5 weights (y=0..4) + x halves (y=5,6) ========
__global__ __launch_bounds__(256) void split6_kernel(
    const float* __restrict__ w0, const float* __restrict__ w1,
    const float* __restrict__ w2, const float* __restrict__ w3,
    const float* __restrict__ w4, const float* __restrict__ x)
{
    const int y = blockIdx.y;
    if (y < 5) {
        const float* srcs[5] = {w0, w1, w2, w3, w4};
        int i = blockIdx.x * 256 + threadIdx.x;           // < 262144
        size_t off = (size_t)y * (D_MODEL * D_MODEL / 4);
        __nv_bfloat162 H[2], L[2];
        split4(((const float4*)srcs[y])[i], H, L);
        ((__nv_bfloat162*)g_Whi)[(off + i) * 2 + 0] = H[0];
        ((__nv_bfloat162*)g_Whi)[(off + i) * 2 + 1] = H[1];
        ((__nv_bfloat162*)g_Wlo)[(off + i) * 2 + 0] = L[0];
        ((__nv_bfloat162*)g_Wlo)[(off + i) * 2 + 1] = L[1];
    } else {
        int i = (y - 5) * (1024 * 256) + blockIdx.x * 256 + threadIdx.x;  // < 524288
        __nv_bfloat162 H[2], L[2];
        split4(((const float4*)x)[i], H, L);
        ((__nv_bfloat162*)g_xhi)[i * 2 + 0] = H[0];
        ((__nv_bfloat162*)g_xhi)[i * 2 + 1] = H[1];
        ((__nv_bfloat162*)g_xlo)[i * 2 + 0] = L[0];
        ((__nv_bfloat162*)g_xlo)[i * 2 + 1] = L[1];
    }
}

// ======== fused 3-term split-bf16 GEMM (round-14 best: full hoist) ==========
__device__ __forceinline__ uint32_t sw64(int row, int j) {
    return (uint32_t)(row * 64 + 16 * (j ^ ((row >> 1) & 3)));
}

__global__ __launch_bounds__(256, 2) void mma_gemm_kernel(
    const __nv_bfloat16* __restrict__ Ahi, const __nv_bfloat16* __restrict__ Alo,
    const float* __restrict__ bias,
    float* C0, float* C1, float* C2, float* C3, int wbase)
{
    extern __shared__ __nv_bfloat16 sm[];
    const int tid = threadIdx.x, lane = tid & 31, wid = tid >> 5;
    const int g = lane >> 2, t = lane & 3;
    const int warpM = (wid & 1) * 64, warpN = (wid >> 1) * 32;
    const int z = blockIdx.z, widx = wbase + z;
    const int m0 = blockIdx.y * 128, n0 = blockIdx.x * 128;

    const __nv_bfloat16* Wh = g_Whi + (size_t)widx * D_MODEL * D_MODEL;
    const __nv_bfloat16* Wl = g_Wlo + (size_t)widx * D_MODEL * D_MODEL;
    float* Cs[4] = {C0, C1, C2, C3};
    float* C = Cs[z];
    const int mode = (widx <= 1) ? 1 : (widx == 3 ? 2 : 0);

    float acc[4][4][4];
    #pragma unroll
    for (int a = 0; a < 4; a++)
        #pragma unroll
        for (int b = 0; b < 4; b++)
            #pragma unroll
            for (int c = 0; c < 4; c++) acc[a][b][c] = 0.f;

    const uint32_t smb = (uint32_t)__cvta_generic_to_shared(sm);
    const int arow = (lane & 7) + ((lane >> 3) & 1) * 8;
    const int ajl  = lane >> 4;
    const int bsel = lane >> 3;
    const int brow = (lane & 7) + ((bsel >> 1) & 1) * 8;
    const int bjl  = bsel & 1;

    auto issue = [&](int kc) {
        const uint32_t sbase = smb + (kc % NST) * STAGE_B;
        #pragma unroll
        for (int r = 0; r < 2; r++) {
            int id = tid + r * 256, row = id >> 2, c = id & 3;
            uint32_t off = sw64(row, c);
            size_t ga = (size_t)(m0 + row) * D_MODEL + kc * KT + c * 8;
            size_t gb = (size_t)(n0 + row) * D_MODEL + kc * KT + c * 8;
            asm volatile("cp.async.cg.shared.global [%0], [%1], 16;" :: "r"(sbase + off),              "l"((const void*)(Ahi + ga)));
            asm volatile("cp.async.cg.shared.global [%0], [%1], 16;" :: "r"(sbase + TILE_B + off),     "l"((const void*)(Alo + ga)));
            asm volatile("cp.async.cg.shared.global [%0], [%1], 16;" :: "r"(sbase + 2 * TILE_B + off), "l"((const void*)(Wh + gb)));
            asm volatile("cp.async.cg.shared.global [%0], [%1], 16;" :: "r"(sbase + 3 * TILE_B + off), "l"((const void*)(Wl + gb)));
        }
        asm volatile("cp.async.commit_group;" ::: "memory");
    };

    issue(0); issue(1);

    for (int it = 0; it < NKC; it++) {
        if (it < NKC - 1) asm volatile("cp.async.wait_group 1;" ::: "memory");
        else              asm volatile("cp.async.wait_group 0;" ::: "memory");
        __syncthreads();
        if (it + 2 < NKC) issue(it + 2);

        const uint32_t sbase = smb + (it % NST) * STAGE_B;
        #pragma unroll
        for (int ks = 0; ks < 2; ks++) {
            uint32_t ahif[4][4], alof[4][4], bfh[4][2], bfl[4][2];
            #pragma unroll
            for (int mt = 0; mt < 4; mt++) {
                uint32_t addr = sbase + sw64(warpM + mt * 16 + arow, ks * 2 + ajl);
                asm volatile("ldmatrix.sync.aligned.m8n8.x4.shared.b16 {%0,%1,%2,%3}, [%4];"
                             : "=r"(ahif[mt][0]), "=r"(ahif[mt][1]), "=r"(ahif[mt][2]), "=r"(ahif[mt][3])
                             : "r"(addr));
            }
            #pragma unroll
            for (int p = 0; p < 2; p++) {
                uint32_t addr = sbase + 2 * TILE_B + sw64(warpN + p * 16 + brow, ks * 2 + bjl);
                asm volatile("ldmatrix.sync.aligned.m8n8.x4.shared.b16 {%0,%1,%2,%3}, [%4];"
                             : "=r"(bfh[2 * p][0]), "=r"(bfh[2 * p][1]),
                               "=r"(bfh[2 * p + 1][0]), "=r"(bfh[2 * p + 1][1])
                             : "r"(addr));
            }
            #pragma unroll
            for (int mt = 0; mt < 4; mt++) {
                uint32_t addr = sbase + TILE_B + sw64(warpM + mt * 16 + arow, ks * 2 + ajl);
                asm volatile("ldmatrix.sync.aligned.m8n8.x4.shared.b16 {%0,%1,%2,%3}, [%4];"
                             : "=r"(alof[mt][0]), "=r"(alof[mt][1]), "=r"(alof[mt][2]), "=r"(alof[mt][3])
                             : "r"(addr));
            }
            #pragma unroll
            for (int p = 0; p < 2; p++) {
                uint32_t addr = sbase + 3 * TILE_B + sw64(warpN + p * 16 + brow, ks * 2 + bjl);
                asm volatile("ldmatrix.sync.aligned.m8n8.x4.shared.b16 {%0,%1,%2,%3}, [%4];"
                             : "=r"(bfl[2 * p][0]), "=r"(bfl[2 * p][1]),
                               "=r"(bfl[2 * p + 1][0]), "=r"(bfl[2 * p + 1][1])
                             : "r"(addr));
            }
            #pragma unroll
            for (int mt = 0; mt < 4; mt++)   // Ahi * Whi
                #pragma unroll
                for (int nt = 0; nt < 4; nt++)
                    asm volatile(
                        "mma.sync.aligned.m16n8k16.row.col.f32.bf16.bf16.f32 "
                        "{%0,%1,%2,%3}, {%4,%5,%6,%7}, {%8,%9}, {%0,%1,%2,%3};"
                        : "+f"(acc[mt][nt][0]), "+f"(acc[mt][nt][1]),
                          "+f"(acc[mt][nt][2]), "+f"(acc[mt][nt][3])
                        : "r"(ahif[mt][0]), "r"(ahif[mt][1]), "r"(ahif[mt][2]), "r"(ahif[mt][3]),
                          "r"(bfh[nt][0]), "r"(bfh[nt][1]));
            #pragma unroll
            for (int mt = 0; mt < 4; mt++)   // Alo * Whi
                #pragma unroll
                for (int nt = 0; nt < 4; nt++)
                    asm volatile(
                        "mma.sync.aligned.m16n8k16.row.col.f32.bf16.bf16.f32 "
                        "{%0,%1,%2,%3}, {%4,%5,%6,%7}, {%8,%9}, {%0,%1,%2,%3};"
                        : "+f"(acc[mt][nt][0]), "+f"(acc[mt][nt][1]),
                          "+f"(acc[mt][nt][2]), "+f"(acc[mt][nt][3])
                        : "r"(alof[mt][0]), "r"(alof[mt][1]), "r"(alof[mt][2]), "r"(alof[mt][3]),
                          "r"(bfh[nt][0]), "r"(bfh[nt][1]));
            #pragma unroll
            for (int mt = 0; mt < 4; mt++)   // Ahi * Wlo
                #pragma unroll
                for (int nt = 0; nt < 4; nt++)
                    asm volatile(
                        "mma.sync.aligned.m16n8k16.row.col.f32.bf16.bf16.f32 "
                        "{%0,%1,%2,%3}, {%4,%5,%6,%7}, {%8,%9}, {%0,%1,%2,%3};"
                        : "+f"(acc[mt][nt][0]), "+f"(acc[mt][nt][1]),
                          "+f"(acc[mt][nt][2]), "+f"(acc[mt][nt][3])
                        : "r"(ahif[mt][0]), "r"(ahif[mt][1]), "r"(ahif[mt][2]), "r"(ahif[mt][3]),
                          "r"(bfl[nt][0]), "r"(bfl[nt][1]));
        }
    }

    #pragma unroll
    for (int mt = 0; mt < 4; mt++) {
        int r0 = m0 + warpM + mt * 16 + g;
        #pragma unroll
        for (int nt = 0; nt < 4; nt++) {
            int c0 = n0 + warpN + nt * 8 + 2 * t;
            float v0 = acc[mt][nt][0], v1 = acc[mt][nt][1];
            float v2 = acc[mt][nt][2], v3 = acc[mt][nt][3];
            if (mode == 1) {
                v0 = softplus_f(v0); v1 = softplus_f(v1);
                v2 = softplus_f(v2); v3 = softplus_f(v3);
            } else if (mode == 2) {
                float b0 = __ldg(&bias[c0]), b1 = __ldg(&bias[c0 + 1]);
                v0 = 1.f / (1.f + expf(-(v0 + b0)));
                v1 = 1.f / (1.f + expf(-(v1 + b1)));
                v2 = 1.f / (1.f + expf(-(v2 + b0)));
                v3 = 1.f / (1.f + expf(-(v3 + b1)));
            }
            float2 p0; p0.x = v0; p0.y = v1;
            float2 p1; p1.x = v2; p1.y = v3;
            *(float2*)&C[(size_t)r0 * D_MODEL + c0]       = p0;
            *(float2*)&C[(size_t)(r0 + 8) * D_MODEL + c0] = p1;
        }
    }
}

// ------------- per-(head,chunk) local state S_c = Kf^T V, z_c = sum kf ------
__global__ __launch_bounds__(256) void chunk_state_kernel() {
    extern __shared__ float smf[];
    float* Kc = smf;
    float* Vc = smf + CHUNK * DH;
    const int head = blockIdx.x >> 4, chunk = blockIdx.x & 15;
    const int t0 = chunk * CHUNK, col0 = head * DH;
    const int tid = threadIdx.x;

    for (int i = tid; i < CHUNK * DH / 4; i += 256) {
        int tt = i >> 4, c4 = (i & 15) << 2;
        *(float4*)&Kc[tt * DH + c4] = *(const float4*)&g_kf[(size_t)(t0 + tt) * D_MODEL + col0 + c4];
        *(float4*)&Vc[tt * DH + c4] = *(const float4*)&g_v [(size_t)(t0 + tt) * D_MODEL + col0 + c4];
    }
    __syncthreads();

    const int dt = (tid >> 4) * 4;
    const int et = (tid & 15) * 4;
    float acc[4][4] = {};
    float z[4] = {};
    #pragma unroll 2
    for (int tt = 0; tt < CHUNK; tt++) {
        float4 k4 = *(float4*)&Kc[tt * DH + dt];
        float4 v4 = *(float4*)&Vc[tt * DH + et];
        z[0] += k4.x; z[1] += k4.y; z[2] += k4.z; z[3] += k4.w;
        acc[0][0] = fmaf(k4.x, v4.x, acc[0][0]); acc[0][1] = fmaf(k4.x, v4.y, acc[0][1]);
        acc[0][2] = fmaf(k4.x, v4.z, acc[0][2]); acc[0][3] = fmaf(k4.x, v4.w, acc[0][3]);
        acc[1][0] = fmaf(k4.y, v4.x, acc[1][0]); acc[1][1] = fmaf(k4.y, v4.y, acc[1][1]);
        acc[1][2] = fmaf(k4.y, v4.z, acc[1][2]); acc[1][3] = fmaf(k4.y, v4.w, acc[1][3]);
        acc[2][0] = fmaf(k4.z, v4.x, acc[2][0]); acc[2][1] = fmaf(k4.z, v4.y, acc[2][1]);
        acc[2][2] = fmaf(k4.z, v4.z, acc[2][2]); acc[2][3] = fmaf(k4.z, v4.w, acc[2][3]);
        acc[3][0] = fmaf(k4.w, v4.x, acc[3][0]); acc[3][1] = fmaf(k4.w, v4.y, acc[3][1]);
        acc[3][2] = fmaf(k4.w, v4.z, acc[3][2]); acc[3][3] = fmaf(k4.w, v4.w, acc[3][3]);
    }
    size_t base = (size_t)blockIdx.x * (DH * DH);
    #pragma unroll
    for (int i = 0; i < 4; i++)
        *(float4*)&g_Sc[base + (dt + i) * DH + et] = *(float4*)&acc[i][0];
    if ((tid & 15) == 0) {
        #pragma unroll
        for (int i = 0; i < 4; i++) g_zc[blockIdx.x * DH + dt + i] = z[i];
    }
}

// ------------- sequential prefix over the 16 chunks (per head) --------------
__global__ __launch_bounds__(256) void prefix_kernel(float* __restrict__ out) {
    const int head = blockIdx.x, tid = threadIdx.x;
    float acc[16] = {};
    for (int c = 0; c < NCHUNK; c++) {
        size_t base = ((size_t)head * NCHUNK + c) * (DH * DH);
        #pragma unroll
        for (int k = 0; k < 16; k++) {
            g_Spre[base + tid + k * 256] = acc[k];
            acc[k] += g_Sc[base + tid + k * 256];
        }
    }
    float* kv_out = out + (size_t)T_SEQ * D_MODEL;
    #pragma unroll
    for (int k = 0; k < 16; k++)
        kv_out[(size_t)head * DH * DH + tid + k * 256] = acc[k];

    if (tid < DH) {
        float z = 0.f;
        for (int c = 0; c < NCHUNK; c++) {
            int base = (head * NCHUNK + c) * DH;
            g_zpre[base + tid] = z;
            z += g_zc[base + tid];
        }
        float* z_out = out + (size_t)T_SEQ * D_MODEL + NH * DH * DH;
        z_out[head * DH + tid] = z;
    }
}

// ------------- attention part A: A=masked qf.kf^T, den, P=qf@Spre -----------
// smem 85 KB -> 2 CTAs/SM. Writes As/P/den to global.
#define QT_STRIDE 132
#define AA_SMEM_FLOATS (DH*QT_STRIDE*2 + DH*DH + DH + CHUNK)

__global__ __launch_bounds__(256) void attnA_kernel() {
    extern __shared__ float smf[];
    float* Qt  = smf;                       // [64][132] k-major, gated qf
    float* Kt  = Qt + DH * QT_STRIDE;       // [64][132]
    float* Ss  = Kt + DH * QT_STRIDE;       // [64][64]
    float* zs  = Ss + DH * DH;              // [64]
    float* den = zs + DH;                   // [128]
    const int bid = blockIdx.x;
    const int head = bid >> 4, chunk = bid & 15;
    const int t0 = chunk * CHUNK, col0 = head * DH;
    const int tid = threadIdx.x;

    for (int i = tid; i < CHUNK * DH / 4; i += 256) {
        int tt = i >> 4, c4 = (i & 15) << 2;
        float4 q4 = *(const float4*)&g_q[(size_t)(t0 + tt) * D_MODEL + col0 + c4];
        float4 g4 = *(const float4*)&g_g[(size_t)(t0 + tt) * D_MODEL + col0 + c4];
        q4.x *= (g4.x + 1e-6f); q4.y *= (g4.y + 1e-6f);
        q4.z *= (g4.z + 1e-6f); q4.w *= (g4.w + 1e-6f);
        Qt[(c4 + 0) * QT_STRIDE + tt] = q4.x; Qt[(c4 + 1) * QT_STRIDE + tt] = q4.y;
        Qt[(c4 + 2) * QT_STRIDE + tt] = q4.z; Qt[(c4 + 3) * QT_STRIDE + tt] = q4.w;
        float4 k4 = *(const float4*)&g_kf[(size_t)(t0 + tt) * D_MODEL + col0 + c4];
        Kt[(c4 + 0) * QT_STRIDE + tt] = k4.x; Kt[(c4 + 1) * QT_STRIDE + tt] = k4.y;
        Kt[(c4 + 2) * QT_STRIDE + tt] = k4.z; Kt[(c4 + 3) * QT_STRIDE + tt] = k4.w;
    }
    {
        size_t base = (size_t)bid * (DH * DH);
        for (int i = tid; i < DH * DH / 4; i += 256)
            *(float4*)&Ss[i * 4] = *(const float4*)&g_Spre[base + i * 4];
    }
    if (tid < DH)    zs[tid]  = g_zpre[bid * DH + tid];
    if (tid < CHUNK) den[tid] = 0.f;
    __syncthreads();

    // Phase A: 8x8 per thread; store masked A to global, rowsums into den
    float* AsG = g_As + (size_t)bid * (CHUNK * CHUNK);
    {
        const int tx = tid & 15, ty = tid >> 4;
        float a[8][8] = {};
        for (int k = 0; k < DH; k++) {
            float qr[8], kr[8];
            *(float4*)&qr[0] = *(float4*)&Qt[k * QT_STRIDE + ty * 8];
            *(float4*)&qr[4] = *(float4*)&Qt[k * QT_STRIDE + ty * 8 + 4];
            *(float4*)&kr[0] = *(float4*)&Kt[k * QT_STRIDE + tx * 8];
            *(float4*)&kr[4] = *(float4*)&Kt[k * QT_STRIDE + tx * 8 + 4];
            #pragma unroll
            for (int i = 0; i < 8; i++)
                #pragma unroll
                for (int j = 0; j < 8; j++)
                    a[i][j] = fmaf(qr[i], kr[j], a[i][j]);
        }
        #pragma unroll
        for (int i = 0; i < 8; i++) {
            int tr = ty * 8 + i;
            float rs = 0.f;
            #pragma unroll
            for (int j = 0; j < 8; j++) {
                int s = tx * 8 + j;
                float vv = (s <= tr) ? a[i][j] : 0.f;
                a[i][j] = vv;
                rs += vv;
            }
            *(float4*)&AsG[(size_t)tr * CHUNK + tx * 8]     = *(float4*)&a[i][0];
            *(float4*)&AsG[(size_t)tr * CHUNK + tx * 8 + 4] = *(float4*)&a[i][4];
            atomicAdd(&den[tr], rs);
        }
    }
    __syncthreads();
    if (tid < CHUNK) {
        float dz = 0.f;
        #pragma unroll 8
        for (int d = 0; d < DH; d++) dz += Qt[d * QT_STRIDE + tid] * zs[d];
        g_den[bid * CHUNK + tid] = den[tid] + dz + 1e-6f;
    }

    // P = qf @ Spre : 4 t-rows x 8 e-cols per thread
    {
        const int es = tid & 7;
        const int tg = tid >> 3;
        const int r0 = tg * 4;
        const int e0 = es * 8;
        float acc[4][8];
        #pragma unroll
        for (int i = 0; i < 4; i++)
            #pragma unroll
            for (int j = 0; j < 8; j++) acc[i][j] = 0.f;
        for (int d = 0; d < DH; d++) {
            float qv[4], sv[8];
            *(float4*)&qv[0] = *(float4*)&Qt[d * QT_STRIDE + r0];
            *(float4*)&sv[0] = *(float4*)&Ss[d * DH + e0];
            *(float4*)&sv[4] = *(float4*)&Ss[d * DH + e0 + 4];
            #pragma unroll
            for (int i = 0; i < 4; i++)
                #pragma unroll
                for (int j = 0; j < 8; j++)
                    acc[i][j] = fmaf(qv[i], sv[j], acc[i][j]);
        }
        float* PG = g_P + (size_t)bid * (CHUNK * DH);
        #pragma unroll
        for (int i = 0; i < 4; i++) {
            *(float4*)&PG[(size_t)(r0 + i) * DH + e0]     = *(float4*)&acc[i][0];
            *(float4*)&PG[(size_t)(r0 + i) * DH + e0 + 4] = *(float4*)&acc[i][4];
        }
    }
}

// ------------- attention part B: out = (P + A@V)/den, bf16 hi/lo store ------
// smem 100.4 KB -> 2 CTAs/SM.
#define AS_STRIDE 132
#define AB_SMEM_FLOATS (CHUNK*AS_STRIDE + CHUNK*DH)

__global__ __launch_bounds__(256) void attnB_kernel() {
    extern __shared__ float smf[];
    float* As = smf;                 // [128][132]
    float* Vs = As + CHUNK * AS_STRIDE;  // [128][64]
    const int bid = blockIdx.x;
    const int head = bid >> 4, chunk = bid & 15;
    const int t0 = chunk * CHUNK, col0 = head * DH;
    const int tid = threadIdx.x;

    {
        const float* AsG = g_As + (size_t)bid * (CHUNK * CHUNK);
        for (int i = tid; i < CHUNK * CHUNK / 4; i += 256) {
            int tt = i >> 5, s4 = (i & 31) << 2;
            *(float4*)&As[tt * AS_STRIDE + s4] = *(const float4*)&AsG[(size_t)tt * CHUNK + s4];
        }
    }
    for (int i = tid; i < CHUNK * DH / 4; i += 256) {
        int tt = i >> 4, c4 = (i & 15) << 2;
        *(float4*)&Vs[tt * DH + c4] = *(const float4*)&g_v[(size_t)(t0 + tt) * D_MODEL + col0 + c4];
    }
    __syncthreads();

    const int es = tid & 7;
    const int tg = tid >> 3;
    const int r0 = tg * 4;
    const int e0 = es * 8;
    const float* PG = g_P + (size_t)bid * (CHUNK * DH);
    float acc[4][8];
    #pragma unroll
    for (int i = 0; i < 4; i++) {
        *(float4*)&acc[i][0] = *(const float4*)&PG[(size_t)(r0 + i) * DH + e0];
        *(float4*)&acc[i][4] = *(const float4*)&PG[(size_t)(r0 + i) * DH + e0 + 4];
    }

    for (int s = 0; s < CHUNK; s += 4) {
        float4 av[4];
        #pragma unroll
        for (int i = 0; i < 4; i++)
            av[i] = *(float4*)&As[(r0 + i) * AS_STRIDE + s];
        #pragma unroll
        for (int ss = 0; ss < 4; ss++) {
            float vv[8];
            *(float4*)&vv[0] = *(float4*)&Vs[(s + ss) * DH + e0];
            *(float4*)&vv[4] = *(float4*)&Vs[(s + ss) * DH + e0 + 4];
            float a0 = (ss == 0) ? av[0].x : (ss == 1) ? av[0].y : (ss == 2) ? av[0].z : av[0].w;
            float a1 = (ss == 0) ? av[1].x : (ss == 1) ? av[1].y : (ss == 2) ? av[1].z : av[1].w;
            float a2 = (ss == 0) ? av[2].x : (ss == 1) ? av[2].y : (ss == 2) ? av[2].z : av[2].w;
            float a3 = (ss == 0) ? av[3].x : (ss == 1) ? av[3].y : (ss == 2) ? av[3].z : av[3].w;
            #pragma unroll
            for (int j = 0; j < 8; j++) {
                acc[0][j] = fmaf(a0, vv[j], acc[0][j]);
                acc[1][j] = fmaf(a1, vv[j], acc[1][j]);
                acc[2][j] = fmaf(a2, vv[j], acc[2][j]);
                acc[3][j] = fmaf(a3, vv[j], acc[3][j]);
            }
        }
    }

    #pragma unroll
    for (int i = 0; i < 4; i++) {
        int tr = r0 + i;
        float dinv = 1.f / g_den[bid * CHUNK + tr];
        size_t obase = ((size_t)(t0 + tr) * D_MODEL + col0 + e0) >> 1;  // bf162 idx
        #pragma unroll
        for (int jj = 0; jj < 4; jj++) {
            float o0 = acc[i][jj * 2 + 0] * dinv;
            float o1 = acc[i][jj * 2 + 1] * dinv;
            __nv_bfloat16 h0 = __float2bfloat16_rn(o0);
            __nv_bfloat16 h1 = __float2bfloat16_rn(o1);
            __nv_bfloat162 H; H.x = h0; H.y = h1;
            __nv_bfloat162 L;
            L.x = __float2bfloat16_rn(o0 - __bfloat162float(h0));
            L.y = __float2bfloat16_rn(o1 - __bfloat162float(h1));
            ((__nv_bfloat162*)g_athi)[obase + jj] = H;
            ((__nv_bfloat162*)g_atlo)[obase + jj] = L;
        }
    }
}

// ---------------------------------------------------------------------------
extern "C" void kernel_launch(void* const* d_in, const int* in_sizes, int n_in,
                              void* d_out, int out_size)
{
    const float* x  = (const float*)d_in[0];
    const float* Wq = (const float*)d_in[1];
    const float* Wk = (const float*)d_in[2];
    const float* Wv = (const float*)d_in[3];
    const float* Wo = (const float*)d_in[4];
    const float* Wg = (const float*)d_in[5];
    const float* bg = (const float*)d_in[6];
    float* out = (float*)d_out;

    float *qb, *gb, *kb, *vb;
    cudaGetSymbolAddress((void**)&qb, g_q);
    cudaGetSymbolAddress((void**)&gb, g_g);
    cudaGetSymbolAddress((void**)&kb, g_kf);
    cudaGetSymbolAddress((void**)&vb, g_v);
    __nv_bfloat16 *xhi, *xlo, *athi, *atlo;
    cudaGetSymbolAddress((void**)&xhi, g_xhi);
    cudaGetSymbolAddress((void**)&xlo, g_xlo);
    cudaGetSymbolAddress((void**)&athi, g_athi);
    cudaGetSymbolAddress((void**)&atlo, g_atlo);

    const int cs_smem = CHUNK * DH * 2 * sizeof(float);
    const int aa_smem = AA_SMEM_FLOATS * sizeof(float);
    const int ab_smem = AB_SMEM_FLOATS * sizeof(float);
    const int gm_smem = NST * STAGE_B;
    cudaFuncSetAttribute(chunk_state_kernel, cudaFuncAttributeMaxDynamicSharedMemorySize, cs_smem);
    cudaFuncSetAttribute(attnA_kernel, cudaFuncAttributeMaxDynamicSharedMemorySize, aa_smem);
    cudaFuncSetAttribute(attnB_kernel, cudaFuncAttributeMaxDynamicSharedMemorySize, ab_smem);
    cudaFuncSetAttribute(mma_gemm_kernel, cudaFuncAttributeMaxDynamicSharedMemorySize, gm_smem);

    // launch 0: ALL splits (5 weights + x) in one grid
    {
        dim3 grid(1024, 7);
        split6_kernel<<<grid, 256>>>(Wq, Wk, Wv, Wg, Wo, x);
    }
    // launch 1: fused Q/K/V/G projections
    {
        dim3 grid(D_MODEL / 128, T_SEQ / 128, 4);
        mma_gemm_kernel<<<grid, 256, gm_smem>>>(xhi, xlo, bg, qb, kb, vb, gb, 0);
    }
    // launches 2..5: attention pipeline
    chunk_state_kernel<<<NH * NCHUNK, 256, cs_smem>>>();
    prefix_kernel<<<NH, 256>>>(out);
    attnA_kernel<<<NH * NCHUNK, 256, aa_smem>>>();
    attnB_kernel<<<NH * NCHUNK, 256, ab_smem>>>();
    // launch 6: output projection
    {
        dim3 grid(D_MODEL / 128, T_SEQ / 128, 1);
        mma_gemm_kernel<<<grid, 256, gm_smem>>>(athi, atlo, nullptr, out, out, out, out, 4);
    }
}

// round 16
// speedup vs baseline: 1.1609x; 1.0781x over previous
#include <cuda_runtime.h>
#include <cuda_bf16.h>
#include <math.h>
#include <stdint.h>

#define T_SEQ   2048
#define D_MODEL 1024
#define NH      16
#define DH      64
#define CHUNK   128
#define NCHUNK  (T_SEQ / CHUNK)   // 16
#define KT      32
#define NKC     (D_MODEL / KT)    // 32
#define TILE_B  8192
#define STAGE_B 32768
#define NST     3

// ---------------- scratch (static __device__ arrays; no allocation) ----------
__device__ __align__(256) float g_q  [T_SEQ * D_MODEL];
__device__ __align__(256) float g_g  [T_SEQ * D_MODEL];
__device__ __align__(256) float g_kf [T_SEQ * D_MODEL];
__device__ __align__(256) float g_v  [T_SEQ * D_MODEL];
__device__ __align__(256) float g_Sc  [NH * NCHUNK * DH * DH];
__device__ __align__(256) float g_Spre[NH * NCHUNK * DH * DH];
__device__ __align__(256) float g_zc  [NH * NCHUNK * DH];
__device__ __align__(256) float g_zpre[NH * NCHUNK * DH];
__device__ __align__(256) float g_As [NH * NCHUNK * CHUNK * CHUNK];
__device__ __align__(256) float g_P  [NH * NCHUNK * CHUNK * DH];
__device__ __align__(256) float g_den[NH * NCHUNK * CHUNK];
__device__ __align__(256) __nv_bfloat16 g_xhi [T_SEQ * D_MODEL];
__device__ __align__(256) __nv_bfloat16 g_xlo [T_SEQ * D_MODEL];
__device__ __align__(256) __nv_bfloat16 g_Whi [5 * D_MODEL * D_MODEL];
__device__ __align__(256) __nv_bfloat16 g_Wlo [5 * D_MODEL * D_MODEL];
__device__ __align__(256) __nv_bfloat16 g_athi[T_SEQ * D_MODEL];
__device__ __align__(256) __nv_bfloat16 g_atlo[T_SEQ * D_MODEL];

__device__ __forceinline__ float softplus_f(float x) {
    return (x > 20.f) ? x : log1pf(expf(x));
}

__device__ __forceinline__ void split4(float4 v, __nv_bfloat162* hi2, __nv_bfloat162* lo2) {
    __nv_bfloat16 h0 = __float2bfloat16_rn(v.x), h1 = __float2bfloat16_rn(v.y);
    __nv_bfloat16 h2 = __float2bfloat16_rn(v.z), h3 = __float2bfloat16_rn(v.w);
    hi2[0].x = h0; hi2[0].y = h1; hi2[1].x = h2; hi2[1].y = h3;
    lo2[0].x = __float2bfloat16_rn(v.x - __bfloat162float(h0));
    lo2[0].y = __float2bfloat16_rn(v.y - __bfloat162float(h1));
    lo2[1].x = __float2bfloat16_rn(v.z - __bfloat162float(h2));
    lo2[1].y = __float2bfloat16_rn(v.w - __bfloat162float(h3));
}

// =========== one-launch split: 5 weights (y=0..4) + x halves (y=5,6) ========
__global__ __launch_bounds__(256) void split6_kernel(
    const float* __restrict__ w0, const float* __restrict__ w1,
    const float* __restrict__ w2, const float* __restrict__ w3,
    const float* __restrict__ w4, const float* __restrict__ x)
{
    const int y = blockIdx.y;
    if (y < 5) {
        const float* srcs[5] = {w0, w1, w2, w3, w4};
        int i = blockIdx.x * 256 + threadIdx.x;
        size_t off = (size_t)y * (D_MODEL * D_MODEL / 4);
        __nv_bfloat162 H[2], L[2];
        split4(((const float4*)srcs[y])[i], H, L);
        ((__nv_bfloat162*)g_Whi)[(off + i) * 2 + 0] = H[0];
        ((__nv_bfloat162*)g_Whi)[(off + i) * 2 + 1] = H[1];
        ((__nv_bfloat162*)g_Wlo)[(off + i) * 2 + 0] = L[0];
        ((__nv_bfloat162*)g_Wlo)[(off + i) * 2 + 1] = L[1];
    } else {
        int i = (y - 5) * (1024 * 256) + blockIdx.x * 256 + threadIdx.x;
        __nv_bfloat162 H[2], L[2];
        split4(((const float4*)x)[i], H, L);
        ((__nv_bfloat162*)g_xhi)[i * 2 + 0] = H[0];
        ((__nv_bfloat162*)g_xhi)[i * 2 + 1] = H[1];
        ((__nv_bfloat162*)g_xlo)[i * 2 + 0] = L[0];
        ((__nv_bfloat162*)g_xlo)[i * 2 + 1] = L[1];
    }
}

// ======== fused 3-term split-bf16 GEMM (round-14 best: full hoist) ==========
__device__ __forceinline__ uint32_t sw64(int row, int j) {
    return (uint32_t)(row * 64 + 16 * (j ^ ((row >> 1) & 3)));
}

__global__ __launch_bounds__(256, 2) void mma_gemm_kernel(
    const __nv_bfloat16* __restrict__ Ahi, const __nv_bfloat16* __restrict__ Alo,
    const float* __restrict__ bias,
    float* C0, float* C1, float* C2, float* C3, int wbase)
{
    extern __shared__ __nv_bfloat16 sm[];
    const int tid = threadIdx.x, lane = tid & 31, wid = tid >> 5;
    const int g = lane >> 2, t = lane & 3;
    const int warpM = (wid & 1) * 64, warpN = (wid >> 1) * 32;
    const int z = blockIdx.z, widx = wbase + z;
    const int m0 = blockIdx.y * 128, n0 = blockIdx.x * 128;

    const __nv_bfloat16* Wh = g_Whi + (size_t)widx * D_MODEL * D_MODEL;
    const __nv_bfloat16* Wl = g_Wlo + (size_t)widx * D_MODEL * D_MODEL;
    float* Cs[4] = {C0, C1, C2, C3};
    float* C = Cs[z];
    const int mode = (widx <= 1) ? 1 : (widx == 3 ? 2 : 0);

    float acc[4][4][4];
    #pragma unroll
    for (int a = 0; a < 4; a++)
        #pragma unroll
        for (int b = 0; b < 4; b++)
            #pragma unroll
            for (int c = 0; c < 4; c++) acc[a][b][c] = 0.f;

    const uint32_t smb = (uint32_t)__cvta_generic_to_shared(sm);
    const int arow = (lane & 7) + ((lane >> 3) & 1) * 8;
    const int ajl  = lane >> 4;
    const int bsel = lane >> 3;
    const int brow = (lane & 7) + ((bsel >> 1) & 1) * 8;
    const int bjl  = bsel & 1;

    auto issue = [&](int kc) {
        const uint32_t sbase = smb + (kc % NST) * STAGE_B;
        #pragma unroll
        for (int r = 0; r < 2; r++) {
            int id = tid + r * 256, row = id >> 2, c = id & 3;
            uint32_t off = sw64(row, c);
            size_t ga = (size_t)(m0 + row) * D_MODEL + kc * KT + c * 8;
            size_t gb = (size_t)(n0 + row) * D_MODEL + kc * KT + c * 8;
            asm volatile("cp.async.cg.shared.global [%0], [%1], 16;" :: "r"(sbase + off),              "l"((const void*)(Ahi + ga)));
            asm volatile("cp.async.cg.shared.global [%0], [%1], 16;" :: "r"(sbase + TILE_B + off),     "l"((const void*)(Alo + ga)));
            asm volatile("cp.async.cg.shared.global [%0], [%1], 16;" :: "r"(sbase + 2 * TILE_B + off), "l"((const void*)(Wh + gb)));
            asm volatile("cp.async.cg.shared.global [%0], [%1], 16;" :: "r"(sbase + 3 * TILE_B + off), "l"((const void*)(Wl + gb)));
        }
        asm volatile("cp.async.commit_group;" ::: "memory");
    };

    issue(0); issue(1);

    for (int it = 0; it < NKC; it++) {
        if (it < NKC - 1) asm volatile("cp.async.wait_group 1;" ::: "memory");
        else              asm volatile("cp.async.wait_group 0;" ::: "memory");
        __syncthreads();
        if (it + 2 < NKC) issue(it + 2);

        const uint32_t sbase = smb + (it % NST) * STAGE_B;
        #pragma unroll
        for (int ks = 0; ks < 2; ks++) {
            uint32_t ahif[4][4], alof[4][4], bfh[4][2], bfl[4][2];
            #pragma unroll
            for (int mt = 0; mt < 4; mt++) {
                uint32_t addr = sbase + sw64(warpM + mt * 16 + arow, ks * 2 + ajl);
                asm volatile("ldmatrix.sync.aligned.m8n8.x4.shared.b16 {%0,%1,%2,%3}, [%4];"
                             : "=r"(ahif[mt][0]), "=r"(ahif[mt][1]), "=r"(ahif[mt][2]), "=r"(ahif[mt][3])
                             : "r"(addr));
            }
            #pragma unroll
            for (int p = 0; p < 2; p++) {
                uint32_t addr = sbase + 2 * TILE_B + sw64(warpN + p * 16 + brow, ks * 2 + bjl);
                asm volatile("ldmatrix.sync.aligned.m8n8.x4.shared.b16 {%0,%1,%2,%3}, [%4];"
                             : "=r"(bfh[2 * p][0]), "=r"(bfh[2 * p][1]),
                               "=r"(bfh[2 * p + 1][0]), "=r"(bfh[2 * p + 1][1])
                             : "r"(addr));
            }
            #pragma unroll
            for (int mt = 0; mt < 4; mt++) {
                uint32_t addr = sbase + TILE_B + sw64(warpM + mt * 16 + arow, ks * 2 + ajl);
                asm volatile("ldmatrix.sync.aligned.m8n8.x4.shared.b16 {%0,%1,%2,%3}, [%4];"
                             : "=r"(alof[mt][0]), "=r"(alof[mt][1]), "=r"(alof[mt][2]), "=r"(alof[mt][3])
                             : "r"(addr));
            }
            #pragma unroll
            for (int p = 0; p < 2; p++) {
                uint32_t addr = sbase + 3 * TILE_B + sw64(warpN + p * 16 + brow, ks * 2 + bjl);
                asm volatile("ldmatrix.sync.aligned.m8n8.x4.shared.b16 {%0,%1,%2,%3}, [%4];"
                             : "=r"(bfl[2 * p][0]), "=r"(bfl[2 * p][1]),
                               "=r"(bfl[2 * p + 1][0]), "=r"(bfl[2 * p + 1][1])
                             : "r"(addr));
            }
            #pragma unroll
            for (int mt = 0; mt < 4; mt++)   // Ahi * Whi
                #pragma unroll
                for (int nt = 0; nt < 4; nt++)
                    asm volatile(
                        "mma.sync.aligned.m16n8k16.row.col.f32.bf16.bf16.f32 "
                        "{%0,%1,%2,%3}, {%4,%5,%6,%7}, {%8,%9}, {%0,%1,%2,%3};"
                        : "+f"(acc[mt][nt][0]), "+f"(acc[mt][nt][1]),
                          "+f"(acc[mt][nt][2]), "+f"(acc[mt][nt][3])
                        : "r"(ahif[mt][0]), "r"(ahif[mt][1]), "r"(ahif[mt][2]), "r"(ahif[mt][3]),
                          "r"(bfh[nt][0]), "r"(bfh[nt][1]));
            #pragma unroll
            for (int mt = 0; mt < 4; mt++)   // Alo * Whi
                #pragma unroll
                for (int nt = 0; nt < 4; nt++)
                    asm volatile(
                        "mma.sync.aligned.m16n8k16.row.col.f32.bf16.bf16.f32 "
                        "{%0,%1,%2,%3}, {%4,%5,%6,%7}, {%8,%9}, {%0,%1,%2,%3};"
                        : "+f"(acc[mt][nt][0]), "+f"(acc[mt][nt][1]),
                          "+f"(acc[mt][nt][2]), "+f"(acc[mt][nt][3])
                        : "r"(alof[mt][0]), "r"(alof[mt][1]), "r"(alof[mt][2]), "r"(alof[mt][3]),
                          "r"(bfh[nt][0]), "r"(bfh[nt][1]));
            #pragma unroll
            for (int mt = 0; mt < 4; mt++)   // Ahi * Wlo
                #pragma unroll
                for (int nt = 0; nt < 4; nt++)
                    asm volatile(
                        "mma.sync.aligned.m16n8k16.row.col.f32.bf16.bf16.f32 "
                        "{%0,%1,%2,%3}, {%4,%5,%6,%7}, {%8,%9}, {%0,%1,%2,%3};"
                        : "+f"(acc[mt][nt][0]), "+f"(acc[mt][nt][1]),
                          "+f"(acc[mt][nt][2]), "+f"(acc[mt][nt][3])
                        : "r"(ahif[mt][0]), "r"(ahif[mt][1]), "r"(ahif[mt][2]), "r"(ahif[mt][3]),
                          "r"(bfl[nt][0]), "r"(bfl[nt][1]));
        }
    }

    #pragma unroll
    for (int mt = 0; mt < 4; mt++) {
        int r0 = m0 + warpM + mt * 16 + g;
        #pragma unroll
        for (int nt = 0; nt < 4; nt++) {
            int c0 = n0 + warpN + nt * 8 + 2 * t;
            float v0 = acc[mt][nt][0], v1 = acc[mt][nt][1];
            float v2 = acc[mt][nt][2], v3 = acc[mt][nt][3];
            if (mode == 1) {
                v0 = softplus_f(v0); v1 = softplus_f(v1);
                v2 = softplus_f(v2); v3 = softplus_f(v3);
            } else if (mode == 2) {
                float b0 = __ldg(&bias[c0]), b1 = __ldg(&bias[c0 + 1]);
                v0 = 1.f / (1.f + expf(-(v0 + b0)));
                v1 = 1.f / (1.f + expf(-(v1 + b1)));
                v2 = 1.f / (1.f + expf(-(v2 + b0)));
                v3 = 1.f / (1.f + expf(-(v3 + b1)));
            }
            float2 p0; p0.x = v0; p0.y = v1;
            float2 p1; p1.x = v2; p1.y = v3;
            *(float2*)&C[(size_t)r0 * D_MODEL + c0]       = p0;
            *(float2*)&C[(size_t)(r0 + 8) * D_MODEL + c0] = p1;
        }
    }
}

// ------------- per-(head,chunk) local state S_c = Kf^T V, z_c = sum kf ------
__global__ __launch_bounds__(256) void chunk_state_kernel() {
    extern __shared__ float smf[];
    float* Kc = smf;
    float* Vc = smf + CHUNK * DH;
    const int head = blockIdx.x >> 4, chunk = blockIdx.x & 15;
    const int t0 = chunk * CHUNK, col0 = head * DH;
    const int tid = threadIdx.x;

    for (int i = tid; i < CHUNK * DH / 4; i += 256) {
        int tt = i >> 4, c4 = (i & 15) << 2;
        *(float4*)&Kc[tt * DH + c4] = *(const float4*)&g_kf[(size_t)(t0 + tt) * D_MODEL + col0 + c4];
        *(float4*)&Vc[tt * DH + c4] = *(const float4*)&g_v [(size_t)(t0 + tt) * D_MODEL + col0 + c4];
    }
    __syncthreads();

    const int dt = (tid >> 4) * 4;
    const int et = (tid & 15) * 4;
    float acc[4][4] = {};
    float z[4] = {};
    #pragma unroll 2
    for (int tt = 0; tt < CHUNK; tt++) {
        float4 k4 = *(float4*)&Kc[tt * DH + dt];
        float4 v4 = *(float4*)&Vc[tt * DH + et];
        z[0] += k4.x; z[1] += k4.y; z[2] += k4.z; z[3] += k4.w;
        acc[0][0] = fmaf(k4.x, v4.x, acc[0][0]); acc[0][1] = fmaf(k4.x, v4.y, acc[0][1]);
        acc[0][2] = fmaf(k4.x, v4.z, acc[0][2]); acc[0][3] = fmaf(k4.x, v4.w, acc[0][3]);
        acc[1][0] = fmaf(k4.y, v4.x, acc[1][0]); acc[1][1] = fmaf(k4.y, v4.y, acc[1][1]);
        acc[1][2] = fmaf(k4.y, v4.z, acc[1][2]); acc[1][3] = fmaf(k4.y, v4.w, acc[1][3]);
        acc[2][0] = fmaf(k4.z, v4.x, acc[2][0]); acc[2][1] = fmaf(k4.z, v4.y, acc[2][1]);
        acc[2][2] = fmaf(k4.z, v4.z, acc[2][2]); acc[2][3] = fmaf(k4.z, v4.w, acc[2][3]);
        acc[3][0] = fmaf(k4.w, v4.x, acc[3][0]); acc[3][1] = fmaf(k4.w, v4.y, acc[3][1]);
        acc[3][2] = fmaf(k4.w, v4.z, acc[3][2]); acc[3][3] = fmaf(k4.w, v4.w, acc[3][3]);
    }
    size_t base = (size_t)blockIdx.x * (DH * DH);
    #pragma unroll
    for (int i = 0; i < 4; i++)
        *(float4*)&g_Sc[base + (dt + i) * DH + et] = *(float4*)&acc[i][0];
    if ((tid & 15) == 0) {
        #pragma unroll
        for (int i = 0; i < 4; i++) g_zc[blockIdx.x * DH + dt + i] = z[i];
    }
}

// ------------- parallel prefix: 256 blocks, 1 element/thread, MLP=16 --------
__global__ __launch_bounds__(256) void prefix_kernel(float* __restrict__ out) {
    const int head = blockIdx.x >> 4;
    const int seg  = blockIdx.x & 15;
    const int tid  = threadIdx.x;
    const int e    = seg * 256 + tid;              // element within 64x64 state

    float v[NCHUNK];
    #pragma unroll
    for (int c = 0; c < NCHUNK; c++)
        v[c] = g_Sc[((size_t)head * NCHUNK + c) * (DH * DH) + e];
    float acc = 0.f;
    #pragma unroll
    for (int c = 0; c < NCHUNK; c++) {
        g_Spre[((size_t)head * NCHUNK + c) * (DH * DH) + e] = acc;
        acc += v[c];
    }
    out[(size_t)T_SEQ * D_MODEL + (size_t)head * DH * DH + e] = acc;

    if (seg == 0 && tid < DH) {
        float zv[NCHUNK];
        #pragma unroll
        for (int c = 0; c < NCHUNK; c++)
            zv[c] = g_zc[(head * NCHUNK + c) * DH + tid];
        float z = 0.f;
        #pragma unroll
        for (int c = 0; c < NCHUNK; c++) {
            g_zpre[(head * NCHUNK + c) * DH + tid] = z;
            z += zv[c];
        }
        out[(size_t)T_SEQ * D_MODEL + NH * DH * DH + head * DH + tid] = z;
    }
}

// ------------- attention part A: A=masked qf.kf^T, den, P=qf@Spre -----------
#define QT_STRIDE 132
#define AA_SMEM_FLOATS (DH*QT_STRIDE*2 + DH*DH + DH + CHUNK)

__global__ __launch_bounds__(256) void attnA_kernel() {
    extern __shared__ float smf[];
    float* Qt  = smf;
    float* Kt  = Qt + DH * QT_STRIDE;
    float* Ss  = Kt + DH * QT_STRIDE;
    float* zs  = Ss + DH * DH;
    float* den = zs + DH;
    const int bid = blockIdx.x;
    const int head = bid >> 4, chunk = bid & 15;
    const int t0 = chunk * CHUNK, col0 = head * DH;
    const int tid = threadIdx.x;

    for (int i = tid; i < CHUNK * DH / 4; i += 256) {
        int tt = i >> 4, c4 = (i & 15) << 2;
        float4 q4 = *(const float4*)&g_q[(size_t)(t0 + tt) * D_MODEL + col0 + c4];
        float4 g4 = *(const float4*)&g_g[(size_t)(t0 + tt) * D_MODEL + col0 + c4];
        q4.x *= (g4.x + 1e-6f); q4.y *= (g4.y + 1e-6f);
        q4.z *= (g4.z + 1e-6f); q4.w *= (g4.w + 1e-6f);
        Qt[(c4 + 0) * QT_STRIDE + tt] = q4.x; Qt[(c4 + 1) * QT_STRIDE + tt] = q4.y;
        Qt[(c4 + 2) * QT_STRIDE + tt] = q4.z; Qt[(c4 + 3) * QT_STRIDE + tt] = q4.w;
        float4 k4 = *(const float4*)&g_kf[(size_t)(t0 + tt) * D_MODEL + col0 + c4];
        Kt[(c4 + 0) * QT_STRIDE + tt] = k4.x; Kt[(c4 + 1) * QT_STRIDE + tt] = k4.y;
        Kt[(c4 + 2) * QT_STRIDE + tt] = k4.z; Kt[(c4 + 3) * QT_STRIDE + tt] = k4.w;
    }
    {
        size_t base = (size_t)bid * (DH * DH);
        for (int i = tid; i < DH * DH / 4; i += 256)
            *(float4*)&Ss[i * 4] = *(const float4*)&g_Spre[base + i * 4];
    }
    if (tid < DH)    zs[tid]  = g_zpre[bid * DH + tid];
    if (tid < CHUNK) den[tid] = 0.f;
    __syncthreads();

    float* AsG = g_As + (size_t)bid * (CHUNK * CHUNK);
    {
        const int tx = tid & 15, ty = tid >> 4;
        float a[8][8] = {};
        for (int k = 0; k < DH; k++) {
            float qr[8], kr[8];
            *(float4*)&qr[0] = *(float4*)&Qt[k * QT_STRIDE + ty * 8];
            *(float4*)&qr[4] = *(float4*)&Qt[k * QT_STRIDE + ty * 8 + 4];
            *(float4*)&kr[0] = *(float4*)&Kt[k * QT_STRIDE + tx * 8];
            *(float4*)&kr[4] = *(float4*)&Kt[k * QT_STRIDE + tx * 8 + 4];
            #pragma unroll
            for (int i = 0; i < 8; i++)
                #pragma unroll
                for (int j = 0; j < 8; j++)
                    a[i][j] = fmaf(qr[i], kr[j], a[i][j]);
        }
        #pragma unroll
        for (int i = 0; i < 8; i++) {
            int tr = ty * 8 + i;
            float rs = 0.f;
            #pragma unroll
            for (int j = 0; j < 8; j++) {
                int s = tx * 8 + j;
                float vv = (s <= tr) ? a[i][j] : 0.f;
                a[i][j] = vv;
                rs += vv;
            }
            *(float4*)&AsG[(size_t)tr * CHUNK + tx * 8]     = *(float4*)&a[i][0];
            *(float4*)&AsG[(size_t)tr * CHUNK + tx * 8 + 4] = *(float4*)&a[i][4];
            atomicAdd(&den[tr], rs);
        }
    }
    __syncthreads();
    if (tid < CHUNK) {
        float dz = 0.f;
        #pragma unroll 8
        for (int d = 0; d < DH; d++) dz += Qt[d * QT_STRIDE + tid] * zs[d];
        g_den[bid * CHUNK + tid] = den[tid] + dz + 1e-6f;
    }

    {
        const int es = tid & 7;
        const int tg = tid >> 3;
        const int r0 = tg * 4;
        const int e0 = es * 8;
        float acc[4][8];
        #pragma unroll
        for (int i = 0; i < 4; i++)
            #pragma unroll
            for (int j = 0; j < 8; j++) acc[i][j] = 0.f;
        for (int d = 0; d < DH; d++) {
            float qv[4], sv[8];
            *(float4*)&qv[0] = *(float4*)&Qt[d * QT_STRIDE + r0];
            *(float4*)&sv[0] = *(float4*)&Ss[d * DH + e0];
            *(float4*)&sv[4] = *(float4*)&Ss[d * DH + e0 + 4];
            #pragma unroll
            for (int i = 0; i < 4; i++)
                #pragma unroll
                for (int j = 0; j < 8; j++)
                    acc[i][j] = fmaf(qv[i], sv[j], acc[i][j]);
        }
        float* PG = g_P + (size_t)bid * (CHUNK * DH);
        #pragma unroll
        for (int i = 0; i < 4; i++) {
            *(float4*)&PG[(size_t)(r0 + i) * DH + e0]     = *(float4*)&acc[i][0];
            *(float4*)&PG[(size_t)(r0 + i) * DH + e0 + 4] = *(float4*)&acc[i][4];
        }
    }
}

// ------------- attention part B: out = (P + A@V)/den, bf16 hi/lo store ------
#define AS_STRIDE 132
#define AB_SMEM_FLOATS (CHUNK*AS_STRIDE + CHUNK*DH)

__global__ __launch_bounds__(256) void attnB_kernel() {
    extern __shared__ float smf[];
    float* As = smf;
    float* Vs = As + CHUNK * AS_STRIDE;
    const int bid = blockIdx.x;
    const int head = bid >> 4, chunk = bid & 15;
    const int t0 = chunk * CHUNK, col0 = head * DH;
    const int tid = threadIdx.x;

    {
        const float* AsG = g_As + (size_t)bid * (CHUNK * CHUNK);
        for (int i = tid; i < CHUNK * CHUNK / 4; i += 256) {
            int tt = i >> 5, s4 = (i & 31) << 2;
            *(float4*)&As[tt * AS_STRIDE + s4] = *(const float4*)&AsG[(size_t)tt * CHUNK + s4];
        }
    }
    for (int i = tid; i < CHUNK * DH / 4; i += 256) {
        int tt = i >> 4, c4 = (i & 15) << 2;
        *(float4*)&Vs[tt * DH + c4] = *(const float4*)&g_v[(size_t)(t0 + tt) * D_MODEL + col0 + c4];
    }
    __syncthreads();

    const int es = tid & 7;
    const int tg = tid >> 3;
    const int r0 = tg * 4;
    const int e0 = es * 8;
    const float* PG = g_P + (size_t)bid * (CHUNK * DH);
    float acc[4][8];
    #pragma unroll
    for (int i = 0; i < 4; i++) {
        *(float4*)&acc[i][0] = *(const float4*)&PG[(size_t)(r0 + i) * DH + e0];
        *(float4*)&acc[i][4] = *(const float4*)&PG[(size_t)(r0 + i) * DH + e0 + 4];
    }

    for (int s = 0; s < CHUNK; s += 4) {
        float4 av[4];
        #pragma unroll
        for (int i = 0; i < 4; i++)
            av[i] = *(float4*)&As[(r0 + i) * AS_STRIDE + s];
        #pragma unroll
        for (int ss = 0; ss < 4; ss++) {
            float vv[8];
            *(float4*)&vv[0] = *(float4*)&Vs[(s + ss) * DH + e0];
            *(float4*)&vv[4] = *(float4*)&Vs[(s + ss) * DH + e0 + 4];
            float a0 = (ss == 0) ? av[0].x : (ss == 1) ? av[0].y : (ss == 2) ? av[0].z : av[0].w;
            float a1 = (ss == 0) ? av[1].x : (ss == 1) ? av[1].y : (ss == 2) ? av[1].z : av[1].w;
            float a2 = (ss == 0) ? av[2].x : (ss == 1) ? av[2].y : (ss == 2) ? av[2].z : av[2].w;
            float a3 = (ss == 0) ? av[3].x : (ss == 1) ? av[3].y : (ss == 2) ? av[3].z : av[3].w;
            #pragma unroll
            for (int j = 0; j < 8; j++) {
                acc[0][j] = fmaf(a0, vv[j], acc[0][j]);
                acc[1][j] = fmaf(a1, vv[j], acc[1][j]);
                acc[2][j] = fmaf(a2, vv[j], acc[2][j]);
                acc[3][j] = fmaf(a3, vv[j], acc[3][j]);
            }
        }
    }

    #pragma unroll
    for (int i = 0; i < 4; i++) {
        int tr = r0 + i;
        float dinv = 1.f / g_den[bid * CHUNK + tr];
        size_t obase = ((size_t)(t0 + tr) * D_MODEL + col0 + e0) >> 1;
        #pragma unroll
        for (int jj = 0; jj < 4; jj++) {
            float o0 = acc[i][jj * 2 + 0] * dinv;
            float o1 = acc[i][jj * 2 + 1] * dinv;
            __nv_bfloat16 h0 = __float2bfloat16_rn(o0);
            __nv_bfloat16 h1 = __float2bfloat16_rn(o1);
            __nv_bfloat162 H; H.x = h0; H.y = h1;
            __nv_bfloat162 L;
            L.x = __float2bfloat16_rn(o0 - __bfloat162float(h0));
            L.y = __float2bfloat16_rn(o1 - __bfloat162float(h1));
            ((__nv_bfloat162*)g_athi)[obase + jj] = H;
            ((__nv_bfloat162*)g_atlo)[obase + jj] = L;
        }
    }
}

// ---------------------------------------------------------------------------
extern "C" void kernel_launch(void* const* d_in, const int* in_sizes, int n_in,
                              void* d_out, int out_size)
{
    const float* x  = (const float*)d_in[0];
    const float* Wq = (const float*)d_in[1];
    const float* Wk = (const float*)d_in[2];
    const float* Wv = (const float*)d_in[3];
    const float* Wo = (const float*)d_in[4];
    const float* Wg = (const float*)d_in[5];
    const float* bg = (const float*)d_in[6];
    float* out = (float*)d_out;

    float *qb, *gb, *kb, *vb;
    cudaGetSymbolAddress((void**)&qb, g_q);
    cudaGetSymbolAddress((void**)&gb, g_g);
    cudaGetSymbolAddress((void**)&kb, g_kf);
    cudaGetSymbolAddress((void**)&vb, g_v);
    __nv_bfloat16 *xhi, *xlo, *athi, *atlo;
    cudaGetSymbolAddress((void**)&xhi, g_xhi);
    cudaGetSymbolAddress((void**)&xlo, g_xlo);
    cudaGetSymbolAddress((void**)&athi, g_athi);
    cudaGetSymbolAddress((void**)&atlo, g_atlo);

    const int cs_smem = CHUNK * DH * 2 * sizeof(float);
    const int aa_smem = AA_SMEM_FLOATS * sizeof(float);
    const int ab_smem = AB_SMEM_FLOATS * sizeof(float);
    const int gm_smem = NST * STAGE_B;
    cudaFuncSetAttribute(chunk_state_kernel, cudaFuncAttributeMaxDynamicSharedMemorySize, cs_smem);
    cudaFuncSetAttribute(attnA_kernel, cudaFuncAttributeMaxDynamicSharedMemorySize, aa_smem);
    cudaFuncSetAttribute(attnB_kernel, cudaFuncAttributeMaxDynamicSharedMemorySize, ab_smem);
    cudaFuncSetAttribute(mma_gemm_kernel, cudaFuncAttributeMaxDynamicSharedMemorySize, gm_smem);

    // launch 0: ALL splits (5 weights + x) in one grid
    {
        dim3 grid(1024, 7);
        split6_kernel<<<grid, 256>>>(Wq, Wk, Wv, Wg, Wo, x);
    }
    // launch 1: fused Q/K/V/G projections
    {
        dim3 grid(D_MODEL / 128, T_SEQ / 128, 4);
        mma_gemm_kernel<<<grid, 256, gm_smem>>>(xhi, xlo, bg, qb, kb, vb, gb, 0);
    }
    // launches 2..5: attention pipeline (prefix at idx 3 = ncu capture)
    chunk_state_kernel<<<NH * NCHUNK, 256, cs_smem>>>();
    prefix_kernel<<<NH * 16, 256>>>(out);
    attnA_kernel<<<NH * NCHUNK, 256, aa_smem>>>();
    attnB_kernel<<<NH * NCHUNK, 256, ab_smem>>>();
    // launch 6: output projection
    {
        dim3 grid(D_MODEL / 128, T_SEQ / 128, 1);
        mma_gemm_kernel<<<grid, 256, gm_smem>>>(athi, atlo, nullptr, out, out, out, out, 4);
    }
}

// round 17
// speedup vs baseline: 1.1773x; 1.0142x over previous
#include <cuda_runtime.h>
#include <cuda_bf16.h>
#include <math.h>
#include <stdint.h>

#define T_SEQ   2048
#define D_MODEL 1024
#define NH      16
#define DH      64
#define CHUNK   128
#define NCHUNK  (T_SEQ / CHUNK)   // 16
#define KT      32
#define NKC     (D_MODEL / KT)    // 32
#define TILE_B  8192
#define STAGE_B 32768
#define NST     3

// ---------------- scratch (static __device__ arrays; no allocation) ----------
__device__ __align__(256) float g_q  [T_SEQ * D_MODEL];
__device__ __align__(256) float g_g  [T_SEQ * D_MODEL];
__device__ __align__(256) float g_kf [T_SEQ * D_MODEL];
__device__ __align__(256) float g_v  [T_SEQ * D_MODEL];
__device__ __align__(256) float g_Sc  [NH * NCHUNK * 2 * DH * DH];  // per half-chunk
__device__ __align__(256) float g_Spre[NH * NCHUNK * DH * DH];
__device__ __align__(256) float g_zc  [NH * NCHUNK * 2 * DH];
__device__ __align__(256) float g_zpre[NH * NCHUNK * DH];
__device__ __align__(256) float g_As [NH * NCHUNK * CHUNK * CHUNK];
__device__ __align__(256) float g_P  [NH * NCHUNK * CHUNK * DH];
__device__ __align__(256) float g_den[NH * NCHUNK * CHUNK];
__device__ __align__(256) __nv_bfloat16 g_xhi [T_SEQ * D_MODEL];
__device__ __align__(256) __nv_bfloat16 g_xlo [T_SEQ * D_MODEL];
__device__ __align__(256) __nv_bfloat16 g_Whi [5 * D_MODEL * D_MODEL];
__device__ __align__(256) __nv_bfloat16 g_Wlo [5 * D_MODEL * D_MODEL];
__device__ __align__(256) __nv_bfloat16 g_athi[T_SEQ * D_MODEL];
__device__ __align__(256) __nv_bfloat16 g_atlo[T_SEQ * D_MODEL];

__device__ __forceinline__ float softplus_f(float x) {
    return (x > 20.f) ? x : log1pf(expf(x));
}

__device__ __forceinline__ void split4(float4 v, __nv_bfloat162* hi2, __nv_bfloat162* lo2) {
    __nv_bfloat16 h0 = __float2bfloat16_rn(v.x), h1 = __float2bfloat16_rn(v.y);
    __nv_bfloat16 h2 = __float2bfloat16_rn(v.z), h3 = __float2bfloat16_rn(v.w);
    hi2[0].x = h0; hi2[0].y = h1; hi2[1].x = h2; hi2[1].y = h3;
    lo2[0].x = __float2bfloat16_rn(v.x - __bfloat162float(h0));
    lo2[0].y = __float2bfloat16_rn(v.y - __bfloat162float(h1));
    lo2[1].x = __float2bfloat16_rn(v.z - __bfloat162float(h2));
    lo2[1].y = __float2bfloat16_rn(v.w - __bfloat162float(h3));
}

// =========== one-launch split: 5 weights (y=0..4) + x halves (y=5,6) ========
// each thread handles 2 float4s for ILP
__global__ __launch_bounds__(256) void split6_kernel(
    const float* __restrict__ w0, const float* __restrict__ w1,
    const float* __restrict__ w2, const float* __restrict__ w3,
    const float* __restrict__ w4, const float* __restrict__ x)
{
    const int y = blockIdx.y;
    if (y < 5) {
        const float* srcs[5] = {w0, w1, w2, w3, w4};
        const float* s = srcs[y];
        size_t off = (size_t)y * (D_MODEL * D_MODEL / 4);
        #pragma unroll
        for (int r = 0; r < 2; r++) {
            int i = blockIdx.x * 256 + threadIdx.x + r * 131072;   // < 262144
            __nv_bfloat162 H[2], L[2];
            split4(((const float4*)s)[i], H, L);
            ((__nv_bfloat162*)g_Whi)[(off + i) * 2 + 0] = H[0];
            ((__nv_bfloat162*)g_Whi)[(off + i) * 2 + 1] = H[1];
            ((__nv_bfloat162*)g_Wlo)[(off + i) * 2 + 0] = L[0];
            ((__nv_bfloat162*)g_Wlo)[(off + i) * 2 + 1] = L[1];
        }
    } else {
        #pragma unroll
        for (int r = 0; r < 2; r++) {
            int i = (y - 5) * 262144 + blockIdx.x * 256 + threadIdx.x + r * 131072;
            __nv_bfloat162 H[2], L[2];
            split4(((const float4*)x)[i], H, L);
            ((__nv_bfloat162*)g_xhi)[i * 2 + 0] = H[0];
            ((__nv_bfloat162*)g_xhi)[i * 2 + 1] = H[1];
            ((__nv_bfloat162*)g_xlo)[i * 2 + 0] = L[0];
            ((__nv_bfloat162*)g_xlo)[i * 2 + 1] = L[1];
        }
    }
}

// ======== fused 3-term split-bf16 GEMM (round-14 best: full hoist) ==========
__device__ __forceinline__ uint32_t sw64(int row, int j) {
    return (uint32_t)(row * 64 + 16 * (j ^ ((row >> 1) & 3)));
}

__global__ __launch_bounds__(256, 2) void mma_gemm_kernel(
    const __nv_bfloat16* __restrict__ Ahi, const __nv_bfloat16* __restrict__ Alo,
    const float* __restrict__ bias,
    float* C0, float* C1, float* C2, float* C3, int wbase)
{
    extern __shared__ __nv_bfloat16 sm[];
    const int tid = threadIdx.x, lane = tid & 31, wid = tid >> 5;
    const int g = lane >> 2, t = lane & 3;
    const int warpM = (wid & 1) * 64, warpN = (wid >> 1) * 32;
    const int z = blockIdx.z, widx = wbase + z;
    const int m0 = blockIdx.y * 128, n0 = blockIdx.x * 128;

    const __nv_bfloat16* Wh = g_Whi + (size_t)widx * D_MODEL * D_MODEL;
    const __nv_bfloat16* Wl = g_Wlo + (size_t)widx * D_MODEL * D_MODEL;
    float* Cs[4] = {C0, C1, C2, C3};
    float* C = Cs[z];
    const int mode = (widx <= 1) ? 1 : (widx == 3 ? 2 : 0);

    float acc[4][4][4];
    #pragma unroll
    for (int a = 0; a < 4; a++)
        #pragma unroll
        for (int b = 0; b < 4; b++)
            #pragma unroll
            for (int c = 0; c < 4; c++) acc[a][b][c] = 0.f;

    const uint32_t smb = (uint32_t)__cvta_generic_to_shared(sm);
    const int arow = (lane & 7) + ((lane >> 3) & 1) * 8;
    const int ajl  = lane >> 4;
    const int bsel = lane >> 3;
    const int brow = (lane & 7) + ((bsel >> 1) & 1) * 8;
    const int bjl  = bsel & 1;

    auto issue = [&](int kc) {
        const uint32_t sbase = smb + (kc % NST) * STAGE_B;
        #pragma unroll
        for (int r = 0; r < 2; r++) {
            int id = tid + r * 256, row = id >> 2, c = id & 3;
            uint32_t off = sw64(row, c);
            size_t ga = (size_t)(m0 + row) * D_MODEL + kc * KT + c * 8;
            size_t gb = (size_t)(n0 + row) * D_MODEL + kc * KT + c * 8;
            asm volatile("cp.async.cg.shared.global [%0], [%1], 16;" :: "r"(sbase + off),              "l"((const void*)(Ahi + ga)));
            asm volatile("cp.async.cg.shared.global [%0], [%1], 16;" :: "r"(sbase + TILE_B + off),     "l"((const void*)(Alo + ga)));
            asm volatile("cp.async.cg.shared.global [%0], [%1], 16;" :: "r"(sbase + 2 * TILE_B + off), "l"((const void*)(Wh + gb)));
            asm volatile("cp.async.cg.shared.global [%0], [%1], 16;" :: "r"(sbase + 3 * TILE_B + off), "l"((const void*)(Wl + gb)));
        }
        asm volatile("cp.async.commit_group;" ::: "memory");
    };

    issue(0); issue(1);

    for (int it = 0; it < NKC; it++) {
        if (it < NKC - 1) asm volatile("cp.async.wait_group 1;" ::: "memory");
        else              asm volatile("cp.async.wait_group 0;" ::: "memory");
        __syncthreads();
        if (it + 2 < NKC) issue(it + 2);

        const uint32_t sbase = smb + (it % NST) * STAGE_B;
        #pragma unroll
        for (int ks = 0; ks < 2; ks++) {
            uint32_t ahif[4][4], alof[4][4], bfh[4][2], bfl[4][2];
            #pragma unroll
            for (int mt = 0; mt < 4; mt++) {
                uint32_t addr = sbase + sw64(warpM + mt * 16 + arow, ks * 2 + ajl);
                asm volatile("ldmatrix.sync.aligned.m8n8.x4.shared.b16 {%0,%1,%2,%3}, [%4];"
                             : "=r"(ahif[mt][0]), "=r"(ahif[mt][1]), "=r"(ahif[mt][2]), "=r"(ahif[mt][3])
                             : "r"(addr));
            }
            #pragma unroll
            for (int p = 0; p < 2; p++) {
                uint32_t addr = sbase + 2 * TILE_B + sw64(warpN + p * 16 + brow, ks * 2 + bjl);
                asm volatile("ldmatrix.sync.aligned.m8n8.x4.shared.b16 {%0,%1,%2,%3}, [%4];"
                             : "=r"(bfh[2 * p][0]), "=r"(bfh[2 * p][1]),
                               "=r"(bfh[2 * p + 1][0]), "=r"(bfh[2 * p + 1][1])
                             : "r"(addr));
            }
            #pragma unroll
            for (int mt = 0; mt < 4; mt++) {
                uint32_t addr = sbase + TILE_B + sw64(warpM + mt * 16 + arow, ks * 2 + ajl);
                asm volatile("ldmatrix.sync.aligned.m8n8.x4.shared.b16 {%0,%1,%2,%3}, [%4];"
                             : "=r"(alof[mt][0]), "=r"(alof[mt][1]), "=r"(alof[mt][2]), "=r"(alof[mt][3])
                             : "r"(addr));
            }
            #pragma unroll
            for (int p = 0; p < 2; p++) {
                uint32_t addr = sbase + 3 * TILE_B + sw64(warpN + p * 16 + brow, ks * 2 + bjl);
                asm volatile("ldmatrix.sync.aligned.m8n8.x4.shared.b16 {%0,%1,%2,%3}, [%4];"
                             : "=r"(bfl[2 * p][0]), "=r"(bfl[2 * p][1]),
                               "=r"(bfl[2 * p + 1][0]), "=r"(bfl[2 * p + 1][1])
                             : "r"(addr));
            }
            #pragma unroll
            for (int mt = 0; mt < 4; mt++)   // Ahi * Whi
                #pragma unroll
                for (int nt = 0; nt < 4; nt++)
                    asm volatile(
                        "mma.sync.aligned.m16n8k16.row.col.f32.bf16.bf16.f32 "
                        "{%0,%1,%2,%3}, {%4,%5,%6,%7}, {%8,%9}, {%0,%1,%2,%3};"
                        : "+f"(acc[mt][nt][0]), "+f"(acc[mt][nt][1]),
                          "+f"(acc[mt][nt][2]), "+f"(acc[mt][nt][3])
                        : "r"(ahif[mt][0]), "r"(ahif[mt][1]), "r"(ahif[mt][2]), "r"(ahif[mt][3]),
                          "r"(bfh[nt][0]), "r"(bfh[nt][1]));
            #pragma unroll
            for (int mt = 0; mt < 4; mt++)   // Alo * Whi
                #pragma unroll
                for (int nt = 0; nt < 4; nt++)
                    asm volatile(
                        "mma.sync.aligned.m16n8k16.row.col.f32.bf16.bf16.f32 "
                        "{%0,%1,%2,%3}, {%4,%5,%6,%7}, {%8,%9}, {%0,%1,%2,%3};"
                        : "+f"(acc[mt][nt][0]), "+f"(acc[mt][nt][1]),
                          "+f"(acc[mt][nt][2]), "+f"(acc[mt][nt][3])
                        : "r"(alof[mt][0]), "r"(alof[mt][1]), "r"(alof[mt][2]), "r"(alof[mt][3]),
                          "r"(bfh[nt][0]), "r"(bfh[nt][1]));
            #pragma unroll
            for (int mt = 0; mt < 4; mt++)   // Ahi * Wlo
                #pragma unroll
                for (int nt = 0; nt < 4; nt++)
                    asm volatile(
                        "mma.sync.aligned.m16n8k16.row.col.f32.bf16.bf16.f32 "
                        "{%0,%1,%2,%3}, {%4,%5,%6,%7}, {%8,%9}, {%0,%1,%2,%3};"
                        : "+f"(acc[mt][nt][0]), "+f"(acc[mt][nt][1]),
                          "+f"(acc[mt][nt][2]), "+f"(acc[mt][nt][3])
                        : "r"(ahif[mt][0]), "r"(ahif[mt][1]), "r"(ahif[mt][2]), "r"(ahif[mt][3]),
                          "r"(bfl[nt][0]), "r"(bfl[nt][1]));
        }
    }

    #pragma unroll
    for (int mt = 0; mt < 4; mt++) {
        int r0 = m0 + warpM + mt * 16 + g;
        #pragma unroll
        for (int nt = 0; nt < 4; nt++) {
            int c0 = n0 + warpN + nt * 8 + 2 * t;
            float v0 = acc[mt][nt][0], v1 = acc[mt][nt][1];
            float v2 = acc[mt][nt][2], v3 = acc[mt][nt][3];
            if (mode == 1) {
                v0 = softplus_f(v0); v1 = softplus_f(v1);
                v2 = softplus_f(v2); v3 = softplus_f(v3);
            } else if (mode == 2) {
                float b0 = __ldg(&bias[c0]), b1 = __ldg(&bias[c0 + 1]);
                v0 = 1.f / (1.f + expf(-(v0 + b0)));
                v1 = 1.f / (1.f + expf(-(v1 + b1)));
                v2 = 1.f / (1.f + expf(-(v2 + b0)));
                v3 = 1.f / (1.f + expf(-(v3 + b1)));
            }
            float2 p0; p0.x = v0; p0.y = v1;
            float2 p1; p1.x = v2; p1.y = v3;
            *(float2*)&C[(size_t)r0 * D_MODEL + c0]       = p0;
            *(float2*)&C[(size_t)(r0 + 8) * D_MODEL + c0] = p1;
        }
    }
}

// ------- per-(head,half-chunk) local state: 512 blocks, 32 KB smem ----------
__global__ __launch_bounds__(256) void chunk_state_kernel() {
    extern __shared__ float smf[];
    float* Kc = smf;               // [64][64]
    float* Vc = smf + 64 * DH;     // [64][64]
    const int bid = blockIdx.x;            // hc*2 + half
    const int half = bid & 1, hc = bid >> 1;
    const int head = hc >> 4, chunk = hc & 15;
    const int t0 = chunk * CHUNK + half * 64, col0 = head * DH;
    const int tid = threadIdx.x;

    for (int i = tid; i < 64 * DH / 4; i += 256) {
        int tt = i >> 4, c4 = (i & 15) << 2;
        *(float4*)&Kc[tt * DH + c4] = *(const float4*)&g_kf[(size_t)(t0 + tt) * D_MODEL + col0 + c4];
        *(float4*)&Vc[tt * DH + c4] = *(const float4*)&g_v [(size_t)(t0 + tt) * D_MODEL + col0 + c4];
    }
    __syncthreads();

    const int dt = (tid >> 4) * 4;
    const int et = (tid & 15) * 4;
    float acc[4][4] = {};
    float z[4] = {};
    #pragma unroll 2
    for (int tt = 0; tt < 64; tt++) {
        float4 k4 = *(float4*)&Kc[tt * DH + dt];
        float4 v4 = *(float4*)&Vc[tt * DH + et];
        z[0] += k4.x; z[1] += k4.y; z[2] += k4.z; z[3] += k4.w;
        acc[0][0] = fmaf(k4.x, v4.x, acc[0][0]); acc[0][1] = fmaf(k4.x, v4.y, acc[0][1]);
        acc[0][2] = fmaf(k4.x, v4.z, acc[0][2]); acc[0][3] = fmaf(k4.x, v4.w, acc[0][3]);
        acc[1][0] = fmaf(k4.y, v4.x, acc[1][0]); acc[1][1] = fmaf(k4.y, v4.y, acc[1][1]);
        acc[1][2] = fmaf(k4.y, v4.z, acc[1][2]); acc[1][3] = fmaf(k4.y, v4.w, acc[1][3]);
        acc[2][0] = fmaf(k4.z, v4.x, acc[2][0]); acc[2][1] = fmaf(k4.z, v4.y, acc[2][1]);
        acc[2][2] = fmaf(k4.z, v4.z, acc[2][2]); acc[2][3] = fmaf(k4.z, v4.w, acc[2][3]);
        acc[3][0] = fmaf(k4.w, v4.x, acc[3][0]); acc[3][1] = fmaf(k4.w, v4.y, acc[3][1]);
        acc[3][2] = fmaf(k4.w, v4.z, acc[3][2]); acc[3][3] = fmaf(k4.w, v4.w, acc[3][3]);
    }
    size_t base = (size_t)bid * (DH * DH);
    #pragma unroll
    for (int i = 0; i < 4; i++)
        *(float4*)&g_Sc[base + (dt + i) * DH + et] = *(float4*)&acc[i][0];
    if ((tid & 15) == 0) {
        #pragma unroll
        for (int i = 0; i < 4; i++) g_zc[bid * DH + dt + i] = z[i];
    }
}

// ------------- parallel prefix: sums half-chunk partials while scanning -----
__global__ __launch_bounds__(256) void prefix_kernel(float* __restrict__ out) {
    const int head = blockIdx.x >> 4;
    const int seg  = blockIdx.x & 15;
    const int tid  = threadIdx.x;
    const int e    = seg * 256 + tid;

    float v[NCHUNK];
    #pragma unroll
    for (int c = 0; c < NCHUNK; c++) {
        size_t b = ((size_t)(head * NCHUNK + c) * 2) * (DH * DH) + e;
        v[c] = g_Sc[b] + g_Sc[b + DH * DH];
    }
    float acc = 0.f;
    #pragma unroll
    for (int c = 0; c < NCHUNK; c++) {
        g_Spre[((size_t)head * NCHUNK + c) * (DH * DH) + e] = acc;
        acc += v[c];
    }
    out[(size_t)T_SEQ * D_MODEL + (size_t)head * DH * DH + e] = acc;

    if (seg == 0 && tid < DH) {
        float zv[NCHUNK];
        #pragma unroll
        for (int c = 0; c < NCHUNK; c++) {
            int b = (head * NCHUNK + c) * 2 * DH + tid;
            zv[c] = g_zc[b] + g_zc[b + DH];
        }
        float z = 0.f;
        #pragma unroll
        for (int c = 0; c < NCHUNK; c++) {
            g_zpre[(head * NCHUNK + c) * DH + tid] = z;
            z += zv[c];
        }
        out[(size_t)T_SEQ * D_MODEL + NH * DH * DH + head * DH + tid] = z;
    }
}

// ------------- attention part A: A=masked qf.kf^T, den, P=qf@Spre -----------
#define QT_STRIDE 132
#define AA_SMEM_FLOATS (DH*QT_STRIDE*2 + DH*DH + DH + CHUNK)

__global__ __launch_bounds__(256) void attnA_kernel() {
    extern __shared__ float smf[];
    float* Qt  = smf;
    float* Kt  = Qt + DH * QT_STRIDE;
    float* Ss  = Kt + DH * QT_STRIDE;
    float* zs  = Ss + DH * DH;
    float* den = zs + DH;
    const int bid = blockIdx.x;
    const int head = bid >> 4, chunk = bid & 15;
    const int t0 = chunk * CHUNK, col0 = head * DH;
    const int tid = threadIdx.x;

    for (int i = tid; i < CHUNK * DH / 4; i += 256) {
        int tt = i >> 4, c4 = (i & 15) << 2;
        float4 q4 = *(const float4*)&g_q[(size_t)(t0 + tt) * D_MODEL + col0 + c4];
        float4 g4 = *(const float4*)&g_g[(size_t)(t0 + tt) * D_MODEL + col0 + c4];
        q4.x *= (g4.x + 1e-6f); q4.y *= (g4.y + 1e-6f);
        q4.z *= (g4.z + 1e-6f); q4.w *= (g4.w + 1e-6f);
        Qt[(c4 + 0) * QT_STRIDE + tt] = q4.x; Qt[(c4 + 1) * QT_STRIDE + tt] = q4.y;
        Qt[(c4 + 2) * QT_STRIDE + tt] = q4.z; Qt[(c4 + 3) * QT_STRIDE + tt] = q4.w;
        float4 k4 = *(const float4*)&g_kf[(size_t)(t0 + tt) * D_MODEL + col0 + c4];
        Kt[(c4 + 0) * QT_STRIDE + tt] = k4.x; Kt[(c4 + 1) * QT_STRIDE + tt] = k4.y;
        Kt[(c4 + 2) * QT_STRIDE + tt] = k4.z; Kt[(c4 + 3) * QT_STRIDE + tt] = k4.w;
    }
    {
        size_t base = (size_t)bid * (DH * DH);
        for (int i = tid; i < DH * DH / 4; i += 256)
            *(float4*)&Ss[i * 4] = *(const float4*)&g_Spre[base + i * 4];
    }
    if (tid < DH) zs[tid] = g_zpre[bid * DH + tid];
    __syncthreads();

    float* AsG = g_As + (size_t)bid * (CHUNK * CHUNK);
    {
        const int tx = tid & 15, ty = tid >> 4;
        float a[8][8] = {};
        for (int k = 0; k < DH; k++) {
            float qr[8], kr[8];
            *(float4*)&qr[0] = *(float4*)&Qt[k * QT_STRIDE + ty * 8];
            *(float4*)&qr[4] = *(float4*)&Qt[k * QT_STRIDE + ty * 8 + 4];
            *(float4*)&kr[0] = *(float4*)&Kt[k * QT_STRIDE + tx * 8];
            *(float4*)&kr[4] = *(float4*)&Kt[k * QT_STRIDE + tx * 8 + 4];
            #pragma unroll
            for (int i = 0; i < 8; i++)
                #pragma unroll
                for (int j = 0; j < 8; j++)
                    a[i][j] = fmaf(qr[i], kr[j], a[i][j]);
        }
        #pragma unroll
        for (int i = 0; i < 8; i++) {
            int tr = ty * 8 + i;
            float rs = 0.f;
            #pragma unroll
            for (int j = 0; j < 8; j++) {
                int s = tx * 8 + j;
                float vv = (s <= tr) ? a[i][j] : 0.f;
                a[i][j] = vv;
                rs += vv;
            }
            *(float4*)&AsG[(size_t)tr * CHUNK + tx * 8]     = *(float4*)&a[i][0];
            *(float4*)&AsG[(size_t)tr * CHUNK + tx * 8 + 4] = *(float4*)&a[i][4];
            // reduce rs across the 16 lanes sharing this tr (tx = lane&15)
            #pragma unroll
            for (int off = 8; off; off >>= 1)
                rs += __shfl_xor_sync(0xFFFFFFFFu, rs, off);
            if (tx == 0) den[tr] = rs;
        }
    }
    __syncthreads();
    if (tid < CHUNK) {
        float dz = 0.f;
        #pragma unroll 8
        for (int d = 0; d < DH; d++) dz += Qt[d * QT_STRIDE + tid] * zs[d];
        g_den[bid * CHUNK + tid] = den[tid] + dz + 1e-6f;
    }

    {
        const int es = tid & 7;
        const int tg = tid >> 3;
        const int r0 = tg * 4;
        const int e0 = es * 8;
        float acc[4][8];
        #pragma unroll
        for (int i = 0; i < 4; i++)
            #pragma unroll
            for (int j = 0; j < 8; j++) acc[i][j] = 0.f;
        for (int d = 0; d < DH; d++) {
            float qv[4], sv[8];
            *(float4*)&qv[0] = *(float4*)&Qt[d * QT_STRIDE + r0];
            *(float4*)&sv[0] = *(float4*)&Ss[d * DH + e0];
            *(float4*)&sv[4] = *(float4*)&Ss[d * DH + e0 + 4];
            #pragma unroll
            for (int i = 0; i < 4; i++)
                #pragma unroll
                for (int j = 0; j < 8; j++)
                    acc[i][j] = fmaf(qv[i], sv[j], acc[i][j]);
        }
        float* PG = g_P + (size_t)bid * (CHUNK * DH);
        #pragma unroll
        for (int i = 0; i < 4; i++) {
            *(float4*)&PG[(size_t)(r0 + i) * DH + e0]     = *(float4*)&acc[i][0];
            *(float4*)&PG[(size_t)(r0 + i) * DH + e0 + 4] = *(float4*)&acc[i][4];
        }
    }
}

// ------------- attention part B: out = (P + A@V)/den, bf16 hi/lo store ------
#define AS_STRIDE 132
#define AB_SMEM_FLOATS (CHUNK*AS_STRIDE + CHUNK*DH)

__global__ __launch_bounds__(256) void attnB_kernel() {
    extern __shared__ float smf[];
    float* As = smf;
    float* Vs = As + CHUNK * AS_STRIDE;
    const int bid = blockIdx.x;
    const int head = bid >> 4, chunk = bid & 15;
    const int t0 = chunk * CHUNK, col0 = head * DH;
    const int tid = threadIdx.x;

    {
        const float* AsG = g_As + (size_t)bid * (CHUNK * CHUNK);
        for (int i = tid; i < CHUNK * CHUNK / 4; i += 256) {
            int tt = i >> 5, s4 = (i & 31) << 2;
            *(float4*)&As[tt * AS_STRIDE + s4] = *(const float4*)&AsG[(size_t)tt * CHUNK + s4];
        }
    }
    for (int i = tid; i < CHUNK * DH / 4; i += 256) {
        int tt = i >> 4, c4 = (i & 15) << 2;
        *(float4*)&Vs[tt * DH + c4] = *(const float4*)&g_v[(size_t)(t0 + tt) * D_MODEL + col0 + c4];
    }
    __syncthreads();

    const int es = tid & 7;
    const int tg = tid >> 3;
    const int r0 = tg * 4;
    const int e0 = es * 8;
    const float* PG = g_P + (size_t)bid * (CHUNK * DH);
    float acc[4][8];
    #pragma unroll
    for (int i = 0; i < 4; i++) {
        *(float4*)&acc[i][0] = *(const float4*)&PG[(size_t)(r0 + i) * DH + e0];
        *(float4*)&acc[i][4] = *(const float4*)&PG[(size_t)(r0 + i) * DH + e0 + 4];
    }

    for (int s = 0; s < CHUNK; s += 4) {
        float4 av[4];
        #pragma unroll
        for (int i = 0; i < 4; i++)
            av[i] = *(float4*)&As[(r0 + i) * AS_STRIDE + s];
        #pragma unroll
        for (int ss = 0; ss < 4; ss++) {
            float vv[8];
            *(float4*)&vv[0] = *(float4*)&Vs[(s + ss) * DH + e0];
            *(float4*)&vv[4] = *(float4*)&Vs[(s + ss) * DH + e0 + 4];
            float a0 = (ss == 0) ? av[0].x : (ss == 1) ? av[0].y : (ss == 2) ? av[0].z : av[0].w;
            float a1 = (ss == 0) ? av[1].x : (ss == 1) ? av[1].y : (ss == 2) ? av[1].z : av[1].w;
            float a2 = (ss == 0) ? av[2].x : (ss == 1) ? av[2].y : (ss == 2) ? av[2].z : av[2].w;
            float a3 = (ss == 0) ? av[3].x : (ss == 1) ? av[3].y : (ss == 2) ? av[3].z : av[3].w;
            #pragma unroll
            for (int j = 0; j < 8; j++) {
                acc[0][j] = fmaf(a0, vv[j], acc[0][j]);
                acc[1][j] = fmaf(a1, vv[j], acc[1][j]);
                acc[2][j] = fmaf(a2, vv[j], acc[2][j]);
                acc[3][j] = fmaf(a3, vv[j], acc[3][j]);
            }
        }
    }

    #pragma unroll
    for (int i = 0; i < 4; i++) {
        int tr = r0 + i;
        float dinv = 1.f / g_den[bid * CHUNK + tr];
        size_t obase = ((size_t)(t0 + tr) * D_MODEL + col0 + e0) >> 1;
        #pragma unroll
        for (int jj = 0; jj < 4; jj++) {
            float o0 = acc[i][jj * 2 + 0] * dinv;
            float o1 = acc[i][jj * 2 + 1] * dinv;
            __nv_bfloat16 h0 = __float2bfloat16_rn(o0);
            __nv_bfloat16 h1 = __float2bfloat16_rn(o1);
            __nv_bfloat162 H; H.x = h0; H.y = h1;
            __nv_bfloat162 L;
            L.x = __float2bfloat16_rn(o0 - __bfloat162float(h0));
            L.y = __float2bfloat16_rn(o1 - __bfloat162float(h1));
            ((__nv_bfloat162*)g_athi)[obase + jj] = H;
            ((__nv_bfloat162*)g_atlo)[obase + jj] = L;
        }
    }
}

// ---------------------------------------------------------------------------
extern "C" void kernel_launch(void* const* d_in, const int* in_sizes, int n_in,
                              void* d_out, int out_size)
{
    const float* x  = (const float*)d_in[0];
    const float* Wq = (const float*)d_in[1];
    const float* Wk = (const float*)d_in[2];
    const float* Wv = (const float*)d_in[3];
    const float* Wo = (const float*)d_in[4];
    const float* Wg = (const float*)d_in[5];
    const float* bg = (const float*)d_in[6];
    float* out = (float*)d_out;

    float *qb, *gb, *kb, *vb;
    cudaGetSymbolAddress((void**)&qb, g_q);
    cudaGetSymbolAddress((void**)&gb, g_g);
    cudaGetSymbolAddress((void**)&kb, g_kf);
    cudaGetSymbolAddress((void**)&vb, g_v);
    __nv_bfloat16 *xhi, *xlo, *athi, *atlo;
    cudaGetSymbolAddress((void**)&xhi, g_xhi);
    cudaGetSymbolAddress((void**)&xlo, g_xlo);
    cudaGetSymbolAddress((void**)&athi, g_athi);
    cudaGetSymbolAddress((void**)&atlo, g_atlo);

    const int cs_smem = 64 * DH * 2 * sizeof(float);   // 32 KB
    const int aa_smem = AA_SMEM_FLOATS * sizeof(float);
    const int ab_smem = AB_SMEM_FLOATS * sizeof(float);
    const int gm_smem = NST * STAGE_B;
    cudaFuncSetAttribute(chunk_state_kernel, cudaFuncAttributeMaxDynamicSharedMemorySize, cs_smem);
    cudaFuncSetAttribute(attnA_kernel, cudaFuncAttributeMaxDynamicSharedMemorySize, aa_smem);
    cudaFuncSetAttribute(attnB_kernel, cudaFuncAttributeMaxDynamicSharedMemorySize, ab_smem);
    cudaFuncSetAttribute(mma_gemm_kernel, cudaFuncAttributeMaxDynamicSharedMemorySize, gm_smem);

    // launch 0: ALL splits (5 weights + x) in one grid
    {
        dim3 grid(512, 7);
        split6_kernel<<<grid, 256>>>(Wq, Wk, Wv, Wg, Wo, x);
    }
    // launch 1: fused Q/K/V/G projections
    {
        dim3 grid(D_MODEL / 128, T_SEQ / 128, 4);
        mma_gemm_kernel<<<grid, 256, gm_smem>>>(xhi, xlo, bg, qb, kb, vb, gb, 0);
    }
    // launches 2..5: attention pipeline
    chunk_state_kernel<<<NH * NCHUNK * 2, 256, cs_smem>>>();
    prefix_kernel<<<NH * 16, 256>>>(out);
    attnA_kernel<<<NH * NCHUNK, 256, aa_smem>>>();
    attnB_kernel<<<NH * NCHUNK, 256, ab_smem>>>();
    // launch 6: output projection
    {
        dim3 grid(D_MODEL / 128, T_SEQ / 128, 1);
        mma_gemm_kernel<<<grid, 256, gm_smem>>>(athi, atlo, nullptr, out, out, out, out, 4);
    }
}